// round 2
// baseline (speedup 1.0000x reference)
#include <cuda_runtime.h>
#include <cstdint>

#define N_NODES 50000
#define N_EDGES 800000
#define NODE_IN 16
#define NODE_OUT 3
#define H 128
#define N_LAYERS 3

#define TE 64
#define AS_STRIDE 260   // 256 + 4 pad
#define HS_STRIDE 132   // 128 + 4 pad

// Scratch (alloc-free rule: __device__ globals)
__device__ float g_h[N_NODES * H];
__device__ float g_agg[N_NODES * H];
__device__ int   g_src[N_EDGES];
__device__ int   g_dst[N_EDGES];
__device__ int   g_is64;

// ---------------------------------------------------------------------------
// Edge-index dtype probe: if data is int32 but read as int64, high words are
// random indices (nonzero w.p. ~1-2e-5 each) -> detect reliably over 256 elems.
// ---------------------------------------------------------------------------
__global__ void detect_kernel(const void* __restrict__ ei) {
    if (threadIdx.x == 0 && blockIdx.x == 0) {
        const long long* p = (const long long*)ei;
        int is64 = 1;
        for (int i = 0; i < 256; i++) {
            long long v = p[i];
            if (v < 0 || v >= N_NODES) { is64 = 0; break; }
        }
        g_is64 = is64;
    }
}

__global__ void convert_kernel(const void* __restrict__ ei) {
    int i = blockIdx.x * blockDim.x + threadIdx.x;
    if (i >= 2 * N_EDGES) return;
    int v;
    if (g_is64) v = (int)((const long long*)ei)[i];
    else        v = ((const int*)ei)[i];
    if (i < N_EDGES) g_src[i] = v;
    else             g_dst[i - N_EDGES] = v;
}

// ---------------------------------------------------------------------------
// Encoder: h = x @ enc_w + enc_b       [N,16] @ [16,128]
// ---------------------------------------------------------------------------
__global__ void enc_kernel(const float* __restrict__ x,
                           const float* __restrict__ w,
                           const float* __restrict__ b) {
    int idx = blockIdx.x * blockDim.x + threadIdx.x;
    if (idx >= N_NODES * H) return;
    int node = idx >> 7;
    int c = idx & (H - 1);
    float acc = b[c];
#pragma unroll
    for (int k = 0; k < NODE_IN; k++)
        acc = fmaf(x[node * NODE_IN + k], w[k * H + c], acc);
    g_h[idx] = acc;
}

__global__ void zero_agg_kernel() {
    int idx = blockIdx.x * blockDim.x + threadIdx.x;
    if (idx < N_NODES * H) g_agg[idx] = 0.0f;
}

// ---------------------------------------------------------------------------
// Edge kernel: tile of 64 edges,
//   e = relu([h[src], h[dst]] @ w1 + b1) @ w2 + b2 ; atomicAdd into g_agg[dst]
// 256 threads; thread computes 4 edges x 8 cols. Hs reuses the As region.
// ---------------------------------------------------------------------------
__global__ __launch_bounds__(256, 2)
void edge_kernel(const float* __restrict__ w1, const float* __restrict__ b1,
                 const float* __restrict__ w2, const float* __restrict__ b2) {
    extern __shared__ float smem[];
    float* As = smem;                 // [TE][AS_STRIDE]  (Hs overlays this)
    float* Hs = smem;                 // [TE][HS_STRIDE]

    const int tid = threadIdx.x;
    const int e0 = blockIdx.x * TE;

    // ---- gather: As[e][0:128] = h[src], As[e][128:256] = h[dst]
    {
        int e = tid >> 2;             // 64 edges
        int p = tid & 3;              // 4 quarters of 64 floats
        int src = g_src[e0 + e];
        int dst = g_dst[e0 + e];
        const float4* gp = (p < 2)
            ? (const float4*)&g_h[(size_t)src * H + p * 64]
            : (const float4*)&g_h[(size_t)dst * H + (p - 2) * 64];
        float4* ap = (float4*)&As[e * AS_STRIDE + p * 64];
#pragma unroll
        for (int j = 0; j < 16; j++) ap[j] = gp[j];
    }
    __syncthreads();

    const int ty = tid >> 4;          // 16 row-groups
    const int tx = tid & 15;          // 16 col-groups
    const int erow = ty * 4;          // 4 edges per thread
    const int c0 = tx * 8;            // 8 cols per thread

    // ---- GEMM1: [64,256] @ [256,128] + b1, relu
    float acc[4][8];
#pragma unroll
    for (int i = 0; i < 4; i++)
#pragma unroll
        for (int j = 0; j < 8; j++) acc[i][j] = b1[c0 + j];

#pragma unroll 4
    for (int k = 0; k < 2 * H; k++) {
        float a0 = As[(erow + 0) * AS_STRIDE + k];
        float a1 = As[(erow + 1) * AS_STRIDE + k];
        float a2 = As[(erow + 2) * AS_STRIDE + k];
        float a3 = As[(erow + 3) * AS_STRIDE + k];
        float4 wlo = __ldg((const float4*)&w1[k * H + c0]);
        float4 whi = __ldg((const float4*)&w1[k * H + c0 + 4]);
        float wv[8] = {wlo.x, wlo.y, wlo.z, wlo.w, whi.x, whi.y, whi.z, whi.w};
#pragma unroll
        for (int j = 0; j < 8; j++) {
            acc[0][j] = fmaf(a0, wv[j], acc[0][j]);
            acc[1][j] = fmaf(a1, wv[j], acc[1][j]);
            acc[2][j] = fmaf(a2, wv[j], acc[2][j]);
            acc[3][j] = fmaf(a3, wv[j], acc[3][j]);
        }
    }

    __syncthreads();   // all reads of As done before overlaying Hs
#pragma unroll
    for (int i = 0; i < 4; i++)
#pragma unroll
        for (int j = 0; j < 8; j++)
            Hs[(erow + i) * HS_STRIDE + c0 + j] = fmaxf(acc[i][j], 0.0f);
    __syncthreads();

    // ---- GEMM2: [64,128] @ [128,128] + b2
    float acc2[4][8];
#pragma unroll
    for (int i = 0; i < 4; i++)
#pragma unroll
        for (int j = 0; j < 8; j++) acc2[i][j] = b2[c0 + j];

#pragma unroll 4
    for (int k = 0; k < H; k++) {
        float a0 = Hs[(erow + 0) * HS_STRIDE + k];
        float a1 = Hs[(erow + 1) * HS_STRIDE + k];
        float a2 = Hs[(erow + 2) * HS_STRIDE + k];
        float a3 = Hs[(erow + 3) * HS_STRIDE + k];
        float4 wlo = __ldg((const float4*)&w2[k * H + c0]);
        float4 whi = __ldg((const float4*)&w2[k * H + c0 + 4]);
        float wv[8] = {wlo.x, wlo.y, wlo.z, wlo.w, whi.x, whi.y, whi.z, whi.w};
#pragma unroll
        for (int j = 0; j < 8; j++) {
            acc2[0][j] = fmaf(a0, wv[j], acc2[0][j]);
            acc2[1][j] = fmaf(a1, wv[j], acc2[1][j]);
            acc2[2][j] = fmaf(a2, wv[j], acc2[2][j]);
            acc2[3][j] = fmaf(a3, wv[j], acc2[3][j]);
        }
    }

    // ---- scatter-add messages into g_agg[dst]
#pragma unroll
    for (int i = 0; i < 4; i++) {
        int dst = g_dst[e0 + erow + i];
        float* dp = &g_agg[(size_t)dst * H + c0];
#pragma unroll
        for (int j = 0; j < 8; j++)
            atomicAdd(dp + j, acc2[i][j]);
    }
}

// ---------------------------------------------------------------------------
// Node kernel: h += relu([h, agg] @ w1 + b1) @ w2 + b2
// ---------------------------------------------------------------------------
__global__ __launch_bounds__(256, 2)
void node_kernel(const float* __restrict__ w1, const float* __restrict__ b1,
                 const float* __restrict__ w2, const float* __restrict__ b2) {
    extern __shared__ float smem[];
    float* As = smem;
    float* Hs = smem;

    const int tid = threadIdx.x;
    const int n0 = blockIdx.x * TE;

    {
        int r = tid >> 2;
        int p = tid & 3;
        int node = n0 + r;
        int cn = node < N_NODES ? node : (N_NODES - 1);
        const float4* gp = (p < 2)
            ? (const float4*)&g_h[(size_t)cn * H + p * 64]
            : (const float4*)&g_agg[(size_t)cn * H + (p - 2) * 64];
        float4* ap = (float4*)&As[r * AS_STRIDE + p * 64];
#pragma unroll
        for (int j = 0; j < 16; j++) ap[j] = gp[j];
    }
    __syncthreads();

    const int ty = tid >> 4;
    const int tx = tid & 15;
    const int erow = ty * 4;
    const int c0 = tx * 8;

    float acc[4][8];
#pragma unroll
    for (int i = 0; i < 4; i++)
#pragma unroll
        for (int j = 0; j < 8; j++) acc[i][j] = b1[c0 + j];

#pragma unroll 4
    for (int k = 0; k < 2 * H; k++) {
        float a0 = As[(erow + 0) * AS_STRIDE + k];
        float a1 = As[(erow + 1) * AS_STRIDE + k];
        float a2 = As[(erow + 2) * AS_STRIDE + k];
        float a3 = As[(erow + 3) * AS_STRIDE + k];
        float4 wlo = __ldg((const float4*)&w1[k * H + c0]);
        float4 whi = __ldg((const float4*)&w1[k * H + c0 + 4]);
        float wv[8] = {wlo.x, wlo.y, wlo.z, wlo.w, whi.x, whi.y, whi.z, whi.w};
#pragma unroll
        for (int j = 0; j < 8; j++) {
            acc[0][j] = fmaf(a0, wv[j], acc[0][j]);
            acc[1][j] = fmaf(a1, wv[j], acc[1][j]);
            acc[2][j] = fmaf(a2, wv[j], acc[2][j]);
            acc[3][j] = fmaf(a3, wv[j], acc[3][j]);
        }
    }

    __syncthreads();
#pragma unroll
    for (int i = 0; i < 4; i++)
#pragma unroll
        for (int j = 0; j < 8; j++)
            Hs[(erow + i) * HS_STRIDE + c0 + j] = fmaxf(acc[i][j], 0.0f);
    __syncthreads();

    float acc2[4][8];
#pragma unroll
    for (int i = 0; i < 4; i++)
#pragma unroll
        for (int j = 0; j < 8; j++) acc2[i][j] = b2[c0 + j];

#pragma unroll 4
    for (int k = 0; k < H; k++) {
        float a0 = Hs[(erow + 0) * HS_STRIDE + k];
        float a1 = Hs[(erow + 1) * HS_STRIDE + k];
        float a2 = Hs[(erow + 2) * HS_STRIDE + k];
        float a3 = Hs[(erow + 3) * HS_STRIDE + k];
        float4 wlo = __ldg((const float4*)&w2[k * H + c0]);
        float4 whi = __ldg((const float4*)&w2[k * H + c0 + 4]);
        float wv[8] = {wlo.x, wlo.y, wlo.z, wlo.w, whi.x, whi.y, whi.z, whi.w};
#pragma unroll
        for (int j = 0; j < 8; j++) {
            acc2[0][j] = fmaf(a0, wv[j], acc2[0][j]);
            acc2[1][j] = fmaf(a1, wv[j], acc2[1][j]);
            acc2[2][j] = fmaf(a2, wv[j], acc2[2][j]);
            acc2[3][j] = fmaf(a3, wv[j], acc2[3][j]);
        }
    }

    // residual update (each block owns its rows; no races)
#pragma unroll
    for (int i = 0; i < 4; i++) {
        int node = n0 + erow + i;
        if (node < N_NODES) {
            float* hp = &g_h[(size_t)node * H + c0];
#pragma unroll
            for (int j = 0; j < 8; j++)
                hp[j] += acc2[i][j];
        }
    }
}

// ---------------------------------------------------------------------------
// Decoder: out = h @ dec_w + dec_b    [N,128] @ [128,3]
// ---------------------------------------------------------------------------
__global__ void dec_kernel(const float* __restrict__ w,
                           const float* __restrict__ b,
                           float* __restrict__ out) {
    int idx = blockIdx.x * blockDim.x + threadIdx.x;
    if (idx >= N_NODES * NODE_OUT) return;
    int node = idx / NODE_OUT;
    int j = idx - node * NODE_OUT;
    float acc = b[j];
    const float* hp = &g_h[(size_t)node * H];
#pragma unroll 8
    for (int k = 0; k < H; k++)
        acc = fmaf(hp[k], w[k * NODE_OUT + j], acc);
    out[idx] = acc;
}

// ---------------------------------------------------------------------------
extern "C" void kernel_launch(void* const* d_in, const int* in_sizes, int n_in,
                              void* d_out, int out_size) {
    const float* x      = (const float*)d_in[0];
    const void*  ei     = d_in[1];
    const float* enc_w  = (const float*)d_in[2];
    const float* enc_b  = (const float*)d_in[3];
    const float* dec_w  = (const float*)d_in[4];
    const float* dec_b  = (const float*)d_in[5];
    const float* e_w1   = (const float*)d_in[6];
    const float* e_b1   = (const float*)d_in[7];
    const float* e_w2   = (const float*)d_in[8];
    const float* e_b2   = (const float*)d_in[9];
    const float* n_w1   = (const float*)d_in[10];
    const float* n_b1   = (const float*)d_in[11];
    const float* n_w2   = (const float*)d_in[12];
    const float* n_b2   = (const float*)d_in[13];
    float*       out    = (float*)d_out;

    const size_t smem = (size_t)(TE * AS_STRIDE) * sizeof(float);  // 66,560 B
    static int attr_set = 0;
    if (!attr_set) {
        cudaFuncSetAttribute(edge_kernel, cudaFuncAttributeMaxDynamicSharedMemorySize, (int)smem);
        cudaFuncSetAttribute(node_kernel, cudaFuncAttributeMaxDynamicSharedMemorySize, (int)smem);
        attr_set = 1;
    }

    detect_kernel<<<1, 32>>>(ei);
    convert_kernel<<<(2 * N_EDGES + 255) / 256, 256>>>(ei);

    enc_kernel<<<(N_NODES * H + 255) / 256, 256>>>(x, enc_w, enc_b);

    for (int l = 0; l < N_LAYERS; l++) {
        zero_agg_kernel<<<(N_NODES * H + 255) / 256, 256>>>();
        edge_kernel<<<N_EDGES / TE, 256, smem>>>(
            e_w1 + (size_t)l * 2 * H * H, e_b1 + (size_t)l * H,
            e_w2 + (size_t)l * H * H,     e_b2 + (size_t)l * H);
        node_kernel<<<(N_NODES + TE - 1) / TE, 256, smem>>>(
            n_w1 + (size_t)l * 2 * H * H, n_b1 + (size_t)l * H,
            n_w2 + (size_t)l * H * H,     n_b2 + (size_t)l * H);
    }

    dec_kernel<<<(N_NODES * NODE_OUT + 255) / 256, 256>>>(dec_w, dec_b, out);
}

// round 4
// speedup vs baseline: 1.0944x; 1.0944x over previous
#include <cuda_runtime.h>
#include <cstdint>

#define N_NODES 50000
#define N_EDGES 800000
#define NODE_IN 16
#define NODE_OUT 3
#define H 128
#define N_LAYERS 3

#define TE 64
#define AS_STRIDE 260   // 256 + 4 pad
#define HS_STRIDE 132   // 128 + 4 pad

typedef unsigned long long u64;

// Scratch (alloc-free rule: __device__ globals)
__device__ float g_h[N_NODES * H];
__device__ float g_agg[N_NODES * H];
__device__ int   g_src[N_EDGES];
__device__ int   g_dst[N_EDGES];
__device__ int   g_is64;

// ---------------------------------------------------------------------------
// packed f32x2 helpers (sm_100+ FFMA2 path)
// ---------------------------------------------------------------------------
__device__ __forceinline__ u64 pack2(float lo, float hi) {
    u64 r; asm("mov.b64 %0, {%1, %2};" : "=l"(r) : "f"(lo), "f"(hi)); return r;
}
__device__ __forceinline__ u64 bcast2(float v) { return pack2(v, v); }
__device__ __forceinline__ void ffma2(u64& d, u64 a, u64 b) {
    asm("fma.rn.f32x2 %0, %1, %2, %0;" : "+l"(d) : "l"(a), "l"(b));
}
__device__ __forceinline__ float2 unpk(u64 v) {
    float2 f; asm("mov.b64 {%0, %1}, %2;" : "=f"(f.x), "=f"(f.y) : "l"(v)); return f;
}
__device__ __forceinline__ void red_add_v4(float* p, float a, float b, float c, float d) {
    asm volatile("red.global.add.v4.f32 [%0], {%1, %2, %3, %4};"
                 :: "l"(p), "f"(a), "f"(b), "f"(c), "f"(d) : "memory");
}

// ---------------------------------------------------------------------------
// Edge-index dtype probe (int64 vs int32 delivery)
// ---------------------------------------------------------------------------
__global__ void detect_kernel(const void* __restrict__ ei) {
    if (threadIdx.x == 0 && blockIdx.x == 0) {
        const long long* p = (const long long*)ei;
        int is64 = 1;
        for (int i = 0; i < 256; i++) {
            long long v = p[i];
            if (v < 0 || v >= N_NODES) { is64 = 0; break; }
        }
        g_is64 = is64;
    }
}

__global__ void convert_kernel(const void* __restrict__ ei) {
    int i = blockIdx.x * blockDim.x + threadIdx.x;
    if (i >= 2 * N_EDGES) return;
    int v;
    if (g_is64) v = (int)((const long long*)ei)[i];
    else        v = ((const int*)ei)[i];
    if (i < N_EDGES) g_src[i] = v;
    else             g_dst[i - N_EDGES] = v;
}

// ---------------------------------------------------------------------------
// Encoder: h = x @ enc_w + enc_b       [N,16] @ [16,128]
// ---------------------------------------------------------------------------
__global__ void enc_kernel(const float* __restrict__ x,
                           const float* __restrict__ w,
                           const float* __restrict__ b) {
    int idx = blockIdx.x * blockDim.x + threadIdx.x;
    if (idx >= N_NODES * H) return;
    int node = idx >> 7;
    int c = idx & (H - 1);
    float acc = b[c];
#pragma unroll
    for (int k = 0; k < NODE_IN; k++)
        acc = fmaf(x[node * NODE_IN + k], w[k * H + c], acc);
    g_h[idx] = acc;
}

__global__ void zero_agg_kernel() {
    int idx = blockIdx.x * blockDim.x + threadIdx.x;
    if (idx < N_NODES * H) g_agg[idx] = 0.0f;
}

// ---------------------------------------------------------------------------
// Edge kernel: tile of 64 edges,
//   e = relu([h[src], h[dst]] @ w1 + b1) @ w2 + b2 ; red.add into g_agg[dst]
// 256 threads; thread computes 4 edges x 8 cols (4 f32x2 col-pairs).
// ---------------------------------------------------------------------------
__global__ __launch_bounds__(256, 2)
void edge_kernel(const float* __restrict__ w1, const float* __restrict__ b1,
                 const float* __restrict__ w2, const float* __restrict__ b2) {
    extern __shared__ float smem[];
    float* As = smem;                 // [TE][AS_STRIDE]  (Hs overlays this)
    float* Hs = smem;                 // [TE][HS_STRIDE]

    const int tid = threadIdx.x;
    const int e0 = blockIdx.x * TE;

    // ---- gather: As[e][0:128] = h[src], As[e][128:256] = h[dst]
    {
        int e = tid >> 2;             // 64 edges
        int p = tid & 3;              // 4 quarters of 64 floats
        int src = g_src[e0 + e];
        int dst = g_dst[e0 + e];
        const float4* gp = (p < 2)
            ? (const float4*)&g_h[(size_t)src * H + p * 64]
            : (const float4*)&g_h[(size_t)dst * H + (p - 2) * 64];
        float4* ap = (float4*)&As[e * AS_STRIDE + p * 64];
#pragma unroll
        for (int j = 0; j < 16; j++) ap[j] = gp[j];
    }
    __syncthreads();

    const int ty = tid >> 4;          // 16 row-groups
    const int tx = tid & 15;          // 16 col-groups
    const int erow = ty * 4;          // 4 edges per thread
    const int c0 = tx * 8;            // 8 cols per thread

    // ---- GEMM1: [64,256] @ [256,128] + b1, relu (packed f32x2 over col pairs)
    u64 acc[4][4];
#pragma unroll
    for (int j = 0; j < 4; j++) {
        u64 bj = pack2(b1[c0 + 2 * j], b1[c0 + 2 * j + 1]);
#pragma unroll
        for (int i = 0; i < 4; i++) acc[i][j] = bj;
    }

#pragma unroll 4
    for (int k = 0; k < 2 * H; k++) {
        u64 a0 = bcast2(As[(erow + 0) * AS_STRIDE + k]);
        u64 a1 = bcast2(As[(erow + 1) * AS_STRIDE + k]);
        u64 a2 = bcast2(As[(erow + 2) * AS_STRIDE + k]);
        u64 a3 = bcast2(As[(erow + 3) * AS_STRIDE + k]);
        ulonglong2 wl = __ldg((const ulonglong2*)&w1[k * H + c0]);
        ulonglong2 wh = __ldg((const ulonglong2*)&w1[k * H + c0 + 4]);
        u64 wp[4] = {wl.x, wl.y, wh.x, wh.y};
#pragma unroll
        for (int j = 0; j < 4; j++) {
            ffma2(acc[0][j], a0, wp[j]);
            ffma2(acc[1][j], a1, wp[j]);
            ffma2(acc[2][j], a2, wp[j]);
            ffma2(acc[3][j], a3, wp[j]);
        }
    }

    __syncthreads();   // all reads of As done before overlaying Hs
#pragma unroll
    for (int i = 0; i < 4; i++)
#pragma unroll
        for (int j = 0; j < 4; j++) {
            float2 v = unpk(acc[i][j]);
            Hs[(erow + i) * HS_STRIDE + c0 + 2 * j]     = fmaxf(v.x, 0.0f);
            Hs[(erow + i) * HS_STRIDE + c0 + 2 * j + 1] = fmaxf(v.y, 0.0f);
        }
    __syncthreads();

    // ---- GEMM2: [64,128] @ [128,128] + b2
    u64 acc2[4][4];
#pragma unroll
    for (int j = 0; j < 4; j++) {
        u64 bj = pack2(b2[c0 + 2 * j], b2[c0 + 2 * j + 1]);
#pragma unroll
        for (int i = 0; i < 4; i++) acc2[i][j] = bj;
    }

#pragma unroll 4
    for (int k = 0; k < H; k++) {
        u64 a0 = bcast2(Hs[(erow + 0) * HS_STRIDE + k]);
        u64 a1 = bcast2(Hs[(erow + 1) * HS_STRIDE + k]);
        u64 a2 = bcast2(Hs[(erow + 2) * HS_STRIDE + k]);
        u64 a3 = bcast2(Hs[(erow + 3) * HS_STRIDE + k]);
        ulonglong2 wl = __ldg((const ulonglong2*)&w2[k * H + c0]);
        ulonglong2 wh = __ldg((const ulonglong2*)&w2[k * H + c0 + 4]);
        u64 wp[4] = {wl.x, wl.y, wh.x, wh.y};
#pragma unroll
        for (int j = 0; j < 4; j++) {
            ffma2(acc2[0][j], a0, wp[j]);
            ffma2(acc2[1][j], a1, wp[j]);
            ffma2(acc2[2][j], a2, wp[j]);
            ffma2(acc2[3][j], a3, wp[j]);
        }
    }

    // ---- scatter-add messages into g_agg[dst] (vector reductions)
#pragma unroll
    for (int i = 0; i < 4; i++) {
        int dst = g_dst[e0 + erow + i];
        float* dp = &g_agg[(size_t)dst * H + c0];
        float2 v0 = unpk(acc2[i][0]);
        float2 v1 = unpk(acc2[i][1]);
        float2 v2 = unpk(acc2[i][2]);
        float2 v3 = unpk(acc2[i][3]);
        red_add_v4(dp,     v0.x, v0.y, v1.x, v1.y);
        red_add_v4(dp + 4, v2.x, v2.y, v3.x, v3.y);
    }
}

// ---------------------------------------------------------------------------
// Node kernel: h += relu([h, agg] @ w1 + b1) @ w2 + b2
// ---------------------------------------------------------------------------
__global__ __launch_bounds__(256, 2)
void node_kernel(const float* __restrict__ w1, const float* __restrict__ b1,
                 const float* __restrict__ w2, const float* __restrict__ b2) {
    extern __shared__ float smem[];
    float* As = smem;
    float* Hs = smem;

    const int tid = threadIdx.x;
    const int n0 = blockIdx.x * TE;

    {
        int r = tid >> 2;
        int p = tid & 3;
        int node = n0 + r;
        int cn = node < N_NODES ? node : (N_NODES - 1);
        const float4* gp = (p < 2)
            ? (const float4*)&g_h[(size_t)cn * H + p * 64]
            : (const float4*)&g_agg[(size_t)cn * H + (p - 2) * 64];
        float4* ap = (float4*)&As[r * AS_STRIDE + p * 64];
#pragma unroll
        for (int j = 0; j < 16; j++) ap[j] = gp[j];
    }
    __syncthreads();

    const int ty = tid >> 4;
    const int tx = tid & 15;
    const int erow = ty * 4;
    const int c0 = tx * 8;

    u64 acc[4][4];
#pragma unroll
    for (int j = 0; j < 4; j++) {
        u64 bj = pack2(b1[c0 + 2 * j], b1[c0 + 2 * j + 1]);
#pragma unroll
        for (int i = 0; i < 4; i++) acc[i][j] = bj;
    }

#pragma unroll 4
    for (int k = 0; k < 2 * H; k++) {
        u64 a0 = bcast2(As[(erow + 0) * AS_STRIDE + k]);
        u64 a1 = bcast2(As[(erow + 1) * AS_STRIDE + k]);
        u64 a2 = bcast2(As[(erow + 2) * AS_STRIDE + k]);
        u64 a3 = bcast2(As[(erow + 3) * AS_STRIDE + k]);
        ulonglong2 wl = __ldg((const ulonglong2*)&w1[k * H + c0]);
        ulonglong2 wh = __ldg((const ulonglong2*)&w1[k * H + c0 + 4]);
        u64 wp[4] = {wl.x, wl.y, wh.x, wh.y};
#pragma unroll
        for (int j = 0; j < 4; j++) {
            ffma2(acc[0][j], a0, wp[j]);
            ffma2(acc[1][j], a1, wp[j]);
            ffma2(acc[2][j], a2, wp[j]);
            ffma2(acc[3][j], a3, wp[j]);
        }
    }

    __syncthreads();
#pragma unroll
    for (int i = 0; i < 4; i++)
#pragma unroll
        for (int j = 0; j < 4; j++) {
            float2 v = unpk(acc[i][j]);
            Hs[(erow + i) * HS_STRIDE + c0 + 2 * j]     = fmaxf(v.x, 0.0f);
            Hs[(erow + i) * HS_STRIDE + c0 + 2 * j + 1] = fmaxf(v.y, 0.0f);
        }
    __syncthreads();

    u64 acc2[4][4];
#pragma unroll
    for (int j = 0; j < 4; j++) {
        u64 bj = pack2(b2[c0 + 2 * j], b2[c0 + 2 * j + 1]);
#pragma unroll
        for (int i = 0; i < 4; i++) acc2[i][j] = bj;
    }

#pragma unroll 4
    for (int k = 0; k < H; k++) {
        u64 a0 = bcast2(Hs[(erow + 0) * HS_STRIDE + k]);
        u64 a1 = bcast2(Hs[(erow + 1) * HS_STRIDE + k]);
        u64 a2 = bcast2(Hs[(erow + 2) * HS_STRIDE + k]);
        u64 a3 = bcast2(Hs[(erow + 3) * HS_STRIDE + k]);
        ulonglong2 wl = __ldg((const ulonglong2*)&w2[k * H + c0]);
        ulonglong2 wh = __ldg((const ulonglong2*)&w2[k * H + c0 + 4]);
        u64 wp[4] = {wl.x, wl.y, wh.x, wh.y};
#pragma unroll
        for (int j = 0; j < 4; j++) {
            ffma2(acc2[0][j], a0, wp[j]);
            ffma2(acc2[1][j], a1, wp[j]);
            ffma2(acc2[2][j], a2, wp[j]);
            ffma2(acc2[3][j], a3, wp[j]);
        }
    }

    // residual update (each block owns its rows; no races)
#pragma unroll
    for (int i = 0; i < 4; i++) {
        int node = n0 + erow + i;
        if (node < N_NODES) {
            float* hp = &g_h[(size_t)node * H + c0];
#pragma unroll
            for (int j = 0; j < 4; j++) {
                float2 v = unpk(acc2[i][j]);
                hp[2 * j]     += v.x;
                hp[2 * j + 1] += v.y;
            }
        }
    }
}

// ---------------------------------------------------------------------------
// Decoder: out = h @ dec_w + dec_b    [N,128] @ [128,3]
// ---------------------------------------------------------------------------
__global__ void dec_kernel(const float* __restrict__ w,
                           const float* __restrict__ b,
                           float* __restrict__ out) {
    int idx = blockIdx.x * blockDim.x + threadIdx.x;
    if (idx >= N_NODES * NODE_OUT) return;
    int node = idx / NODE_OUT;
    int j = idx - node * NODE_OUT;
    float acc = b[j];
    const float* hp = &g_h[(size_t)node * H];
#pragma unroll 8
    for (int k = 0; k < H; k++)
        acc = fmaf(hp[k], w[k * NODE_OUT + j], acc);
    out[idx] = acc;
}

// ---------------------------------------------------------------------------
extern "C" void kernel_launch(void* const* d_in, const int* in_sizes, int n_in,
                              void* d_out, int out_size) {
    const float* x      = (const float*)d_in[0];
    const void*  ei     = d_in[1];
    const float* enc_w  = (const float*)d_in[2];
    const float* enc_b  = (const float*)d_in[3];
    const float* dec_w  = (const float*)d_in[4];
    const float* dec_b  = (const float*)d_in[5];
    const float* e_w1   = (const float*)d_in[6];
    const float* e_b1   = (const float*)d_in[7];
    const float* e_w2   = (const float*)d_in[8];
    const float* e_b2   = (const float*)d_in[9];
    const float* n_w1   = (const float*)d_in[10];
    const float* n_b1   = (const float*)d_in[11];
    const float* n_w2   = (const float*)d_in[12];
    const float* n_b2   = (const float*)d_in[13];
    float*       out    = (float*)d_out;

    const size_t smem = (size_t)(TE * AS_STRIDE) * sizeof(float);  // 66,560 B
    static int attr_set = 0;
    if (!attr_set) {
        cudaFuncSetAttribute(edge_kernel, cudaFuncAttributeMaxDynamicSharedMemorySize, (int)smem);
        cudaFuncSetAttribute(node_kernel, cudaFuncAttributeMaxDynamicSharedMemorySize, (int)smem);
        attr_set = 1;
    }

    detect_kernel<<<1, 32>>>(ei);
    convert_kernel<<<(2 * N_EDGES + 255) / 256, 256>>>(ei);

    enc_kernel<<<(N_NODES * H + 255) / 256, 256>>>(x, enc_w, enc_b);

    for (int l = 0; l < N_LAYERS; l++) {
        zero_agg_kernel<<<(N_NODES * H + 255) / 256, 256>>>();
        edge_kernel<<<N_EDGES / TE, 256, smem>>>(
            e_w1 + (size_t)l * 2 * H * H, e_b1 + (size_t)l * H,
            e_w2 + (size_t)l * H * H,     e_b2 + (size_t)l * H);
        node_kernel<<<(N_NODES + TE - 1) / TE, 256, smem>>>(
            n_w1 + (size_t)l * 2 * H * H, n_b1 + (size_t)l * H,
            n_w2 + (size_t)l * H * H,     n_b2 + (size_t)l * H);
    }

    dec_kernel<<<(N_NODES * NODE_OUT + 255) / 256, 256>>>(dec_w, dec_b, out);
}

// round 6
// speedup vs baseline: 1.5835x; 1.4470x over previous
#include <cuda_runtime.h>
#include <cuda_bf16.h>
#include <cstdint>

#define N_NODES 50000
#define N_EDGES 800000
#define NODE_IN 16
#define NODE_OUT 3
#define H 128
#define N_LAYERS 3

// ---- FFMA2 node-kernel tile params
#define TE 64
#define AS_STRIDE 260
#define HS_STRIDE 132

// ---- mma edge-kernel params
#define ET 128                       // edges per block tile
// smem byte offsets (dynamic)
#define A1H_OFF 0                    // [128][72] bf16 = 18432 B
#define A1L_OFF 18432
#define BH_OFF  36864                // [128][72] bf16
#define BL_OFF  55296
#define A2H_OFF 73728                // [128][136] bf16 = 34816 B
#define A2L_OFF 108544
#define EDGE_SMEM 143360
#define SA1 72                       // bf16 units per row (64 + 8 pad)
#define SB  72
#define SA2 136                      // 128 + 8 pad

typedef unsigned long long u64;

// ---------------------------------------------------------------------------
// Scratch (__device__ globals; alloc-free rule)
// ---------------------------------------------------------------------------
__device__ float g_h[N_NODES * H];
__device__ float g_agg[N_NODES * H];
__device__ int   g_src[N_EDGES];
__device__ int   g_dst[N_EDGES];
__device__ int   g_is64;
// transposed hi/lo-split bf16 edge weights: w^T indexed [c][k]
__device__ __nv_bfloat16 g_w1t[N_LAYERS][2][H][2 * H];
__device__ __nv_bfloat16 g_w2t[N_LAYERS][2][H][H];

// ---------------------------------------------------------------------------
// helpers
// ---------------------------------------------------------------------------
__device__ __forceinline__ uint32_t smem_u32(const void* p) {
    uint32_t a;
    asm("{ .reg .u64 t; cvta.to.shared.u64 t, %1; cvt.u32.u64 %0, t; }"
        : "=r"(a) : "l"(p));
    return a;
}
__device__ __forceinline__ void ldm_x4(uint32_t* r, uint32_t addr) {
    asm volatile("ldmatrix.sync.aligned.m8n8.x4.shared.b16 {%0,%1,%2,%3}, [%4];"
                 : "=r"(r[0]), "=r"(r[1]), "=r"(r[2]), "=r"(r[3]) : "r"(addr));
}
__device__ __forceinline__ void mma_bf16(float* c, const uint32_t* a, const uint32_t* b) {
    asm volatile(
        "mma.sync.aligned.m16n8k16.row.col.f32.bf16.bf16.f32 "
        "{%0,%1,%2,%3}, {%4,%5,%6,%7}, {%8,%9}, {%0,%1,%2,%3};"
        : "+f"(c[0]), "+f"(c[1]), "+f"(c[2]), "+f"(c[3])
        : "r"(a[0]), "r"(a[1]), "r"(a[2]), "r"(a[3]), "r"(b[0]), "r"(b[1]));
}
__device__ __forceinline__ void split2(float a, float b, uint32_t& hi, uint32_t& lo) {
    __nv_bfloat16 ha = __float2bfloat16(a), hb = __float2bfloat16(b);
    hi = (uint32_t)__bfloat16_as_ushort(ha) | ((uint32_t)__bfloat16_as_ushort(hb) << 16);
    __nv_bfloat16 la = __float2bfloat16(a - __bfloat162float(ha));
    __nv_bfloat16 lb = __float2bfloat16(b - __bfloat162float(hb));
    lo = (uint32_t)__bfloat16_as_ushort(la) | ((uint32_t)__bfloat16_as_ushort(lb) << 16);
}
__device__ __forceinline__ void red_add_v2(float* p, float a, float b) {
    asm volatile("red.global.add.v2.f32 [%0], {%1, %2};"
                 :: "l"(p), "f"(a), "f"(b) : "memory");
}
__device__ __forceinline__ void red_add_v4(float* p, float a, float b, float c, float d) {
    asm volatile("red.global.add.v4.f32 [%0], {%1, %2, %3, %4};"
                 :: "l"(p), "f"(a), "f"(b), "f"(c), "f"(d) : "memory");
}
// ---- FFMA2 helpers (node kernel)
__device__ __forceinline__ u64 pack2(float lo, float hi) {
    u64 r; asm("mov.b64 %0, {%1, %2};" : "=l"(r) : "f"(lo), "f"(hi)); return r;
}
__device__ __forceinline__ u64 bcast2(float v) { return pack2(v, v); }
__device__ __forceinline__ void ffma2(u64& d, u64 a, u64 b) {
    asm("fma.rn.f32x2 %0, %1, %2, %0;" : "+l"(d) : "l"(a), "l"(b));
}
__device__ __forceinline__ float2 unpk(u64 v) {
    float2 f; asm("mov.b64 {%0, %1}, %2;" : "=f"(f.x), "=f"(f.y) : "l"(v)); return f;
}

// ---------------------------------------------------------------------------
// dtype probe + convert
// ---------------------------------------------------------------------------
__global__ void detect_kernel(const void* __restrict__ ei) {
    if (threadIdx.x == 0 && blockIdx.x == 0) {
        const long long* p = (const long long*)ei;
        int is64 = 1;
        for (int i = 0; i < 256; i++) {
            long long v = p[i];
            if (v < 0 || v >= N_NODES) { is64 = 0; break; }
        }
        g_is64 = is64;
    }
}

__global__ void convert_kernel(const void* __restrict__ ei) {
    int i = blockIdx.x * blockDim.x + threadIdx.x;
    if (i >= 2 * N_EDGES) return;
    int v;
    if (g_is64) v = (int)((const long long*)ei)[i];
    else        v = ((const int*)ei)[i];
    if (i < N_EDGES) g_src[i] = v;
    else             g_dst[i - N_EDGES] = v;
}

// ---------------------------------------------------------------------------
// Weight prep: transposed hi/lo-split bf16 edge weights (w^T [c][k])
// ---------------------------------------------------------------------------
__global__ void prep_w_kernel(const float* __restrict__ e_w1,
                              const float* __restrict__ e_w2) {
    int idx = blockIdx.x * blockDim.x + threadIdx.x;
    const int W1E = N_LAYERS * 2 * H * H;
    const int W2E = N_LAYERS * H * H;
    if (idx < W1E) {
        int l = idx / (2 * H * H);
        int rem = idx % (2 * H * H);
        int k = rem / H, c = rem % H;
        float w = e_w1[idx];
        __nv_bfloat16 hi = __float2bfloat16(w);
        __nv_bfloat16 lo = __float2bfloat16(w - __bfloat162float(hi));
        g_w1t[l][0][c][k] = hi;
        g_w1t[l][1][c][k] = lo;
    } else if (idx < W1E + W2E) {
        int j = idx - W1E;
        int l = j / (H * H);
        int rem = j % (H * H);
        int k = rem / H, c = rem % H;
        float w = e_w2[j];
        __nv_bfloat16 hi = __float2bfloat16(w);
        __nv_bfloat16 lo = __float2bfloat16(w - __bfloat162float(hi));
        g_w2t[l][0][c][k] = hi;
        g_w2t[l][1][c][k] = lo;
    }
}

// ---------------------------------------------------------------------------
// Encoder (+ zero g_agg)
// ---------------------------------------------------------------------------
__global__ void enc_kernel(const float* __restrict__ x,
                           const float* __restrict__ w,
                           const float* __restrict__ b) {
    int idx = blockIdx.x * blockDim.x + threadIdx.x;
    if (idx >= N_NODES * H) return;
    int node = idx >> 7;
    int c = idx & (H - 1);
    float acc = b[c];
#pragma unroll
    for (int k = 0; k < NODE_IN; k++)
        acc = fmaf(x[node * NODE_IN + k], w[k * H + c], acc);
    g_h[idx] = acc;
    g_agg[idx] = 0.0f;
}

// ---------------------------------------------------------------------------
// mma chunk: accumulate C += A(hi/lo)[rows r0..r0+31][k 0..63] x B^T cols c0w..+63
// with 3-pass bf16 split. astride/bases in shared address space.
// ---------------------------------------------------------------------------
__device__ __forceinline__ void mma_chunk(
    uint32_t a_hi, uint32_t a_lo, int astride,
    uint32_t b_hi, uint32_t b_lo,
    float C[2][8][4], int r0, int c0w, int lane)
{
    const int arow = lane & 15;
    const int acol = (lane >> 4) * 8;
    const int brow = (lane & 7) + ((lane >> 4) << 3);
    const int bcol = ((lane >> 3) & 1) * 8;
#pragma unroll
    for (int ks = 0; ks < 4; ks++) {
        uint32_t ah[2][4], al[2][4], bh[4][4], bl[4][4];
#pragma unroll
        for (int i = 0; i < 2; i++) {
            uint32_t off = (uint32_t)(((r0 + i * 16 + arow) * astride + ks * 16 + acol) * 2);
            ldm_x4(ah[i], a_hi + off);
            ldm_x4(al[i], a_lo + off);
        }
#pragma unroll
        for (int p = 0; p < 4; p++) {
            uint32_t off = (uint32_t)(((c0w + p * 16 + brow) * SB + ks * 16 + bcol) * 2);
            ldm_x4(bh[p], b_hi + off);
            ldm_x4(bl[p], b_lo + off);
        }
#pragma unroll
        for (int i = 0; i < 2; i++)
#pragma unroll
            for (int p = 0; p < 4; p++) {
                mma_bf16(C[i][2 * p],     ah[i], &bh[p][0]);
                mma_bf16(C[i][2 * p],     ah[i], &bl[p][0]);
                mma_bf16(C[i][2 * p],     al[i], &bh[p][0]);
                mma_bf16(C[i][2 * p + 1], ah[i], &bh[p][2]);
                mma_bf16(C[i][2 * p + 1], ah[i], &bl[p][2]);
                mma_bf16(C[i][2 * p + 1], al[i], &bh[p][2]);
            }
    }
}

// ---------------------------------------------------------------------------
// Edge kernel (tensor-core mma.sync): 128 edges/block, 8 warps
// ---------------------------------------------------------------------------
__global__ __launch_bounds__(256, 1)
void edge_kernel_mma(const float* __restrict__ b1,
                     const float* __restrict__ b2, int layer) {
    extern __shared__ char smem[];
    const uint32_t sbase = smem_u32(smem);
    const int tid = threadIdx.x;
    const int lane = tid & 31;
    const int wid = tid >> 5;
    const int e0 = blockIdx.x * ET;

    // staging role: 2 threads per row
    const int srow = tid >> 1;
    const int shalf = tid & 1;
    const int ssrc = g_src[e0 + srow];
    const int sdst = g_dst[e0 + srow];

    // warp tile: rows r0..r0+31, cols c0w..c0w+63
    const int r0 = (wid >> 1) * 32;
    const int c0w = (wid & 1) * 64;

    float C[2][8][4];
#pragma unroll
    for (int i = 0; i < 2; i++)
#pragma unroll
        for (int j = 0; j < 8; j++)
#pragma unroll
            for (int q = 0; q < 4; q++) C[i][j][q] = 0.0f;

    // ================= GEMM1: K=256 in 4 chunks of 64 =================
    for (int kc = 0; kc < 4; kc++) {
        // stage A chunk: gather + hi/lo split
        {
            int node = (kc < 2) ? ssrc : sdst;
            const float4* hp = (const float4*)&g_h[(size_t)node * H + (kc & 1) * 64 + shalf * 32];
            uint32_t ph[16], pl[16];
#pragma unroll
            for (int i = 0; i < 8; i++) {
                float4 v = hp[i];
                split2(v.x, v.y, ph[2 * i],     pl[2 * i]);
                split2(v.z, v.w, ph[2 * i + 1], pl[2 * i + 1]);
            }
            uint4* dh = (uint4*)(smem + A1H_OFF + srow * (SA1 * 2) + shalf * 64);
            uint4* dl = (uint4*)(smem + A1L_OFF + srow * (SA1 * 2) + shalf * 64);
#pragma unroll
            for (int i = 0; i < 4; i++) {
                dh[i] = make_uint4(ph[4 * i], ph[4 * i + 1], ph[4 * i + 2], ph[4 * i + 3]);
                dl[i] = make_uint4(pl[4 * i], pl[4 * i + 1], pl[4 * i + 2], pl[4 * i + 3]);
            }
        }
        // stage B chunk: w1t[c][kc*64 + ...]
        {
            const float4* sh = (const float4*)&g_w1t[layer][0][srow][kc * 64 + shalf * 32];
            const float4* sl = (const float4*)&g_w1t[layer][1][srow][kc * 64 + shalf * 32];
            float4* dh = (float4*)(smem + BH_OFF + srow * (SB * 2) + shalf * 64);
            float4* dl = (float4*)(smem + BL_OFF + srow * (SB * 2) + shalf * 64);
#pragma unroll
            for (int i = 0; i < 4; i++) { dh[i] = sh[i]; dl[i] = sl[i]; }
        }
        __syncthreads();
        mma_chunk(sbase + A1H_OFF, sbase + A1L_OFF, SA1,
                  sbase + BH_OFF, sbase + BL_OFF, C, r0, c0w, lane);
        __syncthreads();
    }

    // ================= Epilogue1: bias + relu + resplit into A2 =================
#pragma unroll
    for (int i = 0; i < 2; i++)
#pragma unroll
        for (int j = 0; j < 8; j++) {
            int col = c0w + j * 8 + (lane & 3) * 2;
            int row = r0 + i * 16 + (lane >> 2);
            float bb0 = b1[col], bb1 = b1[col + 1];
            uint32_t hi, lo;
            split2(fmaxf(C[i][j][0] + bb0, 0.0f), fmaxf(C[i][j][1] + bb1, 0.0f), hi, lo);
            *(uint32_t*)(smem + A2H_OFF + row * (SA2 * 2) + col * 2) = hi;
            *(uint32_t*)(smem + A2L_OFF + row * (SA2 * 2) + col * 2) = lo;
            split2(fmaxf(C[i][j][2] + bb0, 0.0f), fmaxf(C[i][j][3] + bb1, 0.0f), hi, lo);
            *(uint32_t*)(smem + A2H_OFF + (row + 8) * (SA2 * 2) + col * 2) = hi;
            *(uint32_t*)(smem + A2L_OFF + (row + 8) * (SA2 * 2) + col * 2) = lo;
        }
    __syncthreads();

    // ================= GEMM2: K=128 in 2 chunks =================
#pragma unroll
    for (int i = 0; i < 2; i++)
#pragma unroll
        for (int j = 0; j < 8; j++)
#pragma unroll
            for (int q = 0; q < 4; q++) C[i][j][q] = 0.0f;

    for (int kc = 0; kc < 2; kc++) {
        {
            const float4* sh = (const float4*)&g_w2t[layer][0][srow][kc * 64 + shalf * 32];
            const float4* sl = (const float4*)&g_w2t[layer][1][srow][kc * 64 + shalf * 32];
            float4* dh = (float4*)(smem + BH_OFF + srow * (SB * 2) + shalf * 64);
            float4* dl = (float4*)(smem + BL_OFF + srow * (SB * 2) + shalf * 64);
#pragma unroll
            for (int i = 0; i < 4; i++) { dh[i] = sh[i]; dl[i] = sl[i]; }
        }
        __syncthreads();
        mma_chunk(sbase + A2H_OFF + kc * 128, sbase + A2L_OFF + kc * 128, SA2,
                  sbase + BH_OFF, sbase + BL_OFF, C, r0, c0w, lane);
        __syncthreads();
    }

    // ================= Epilogue2: bias + scatter-add =================
#pragma unroll
    for (int i = 0; i < 2; i++) {
        int row = r0 + i * 16 + (lane >> 2);
        int d0 = g_dst[e0 + row];
        int d1 = g_dst[e0 + row + 8];
#pragma unroll
        for (int j = 0; j < 8; j++) {
            int col = c0w + j * 8 + (lane & 3) * 2;
            float bb0 = b2[col], bb1 = b2[col + 1];
            red_add_v2(&g_agg[(size_t)d0 * H + col], C[i][j][0] + bb0, C[i][j][1] + bb1);
            red_add_v2(&g_agg[(size_t)d1 * H + col], C[i][j][2] + bb0, C[i][j][3] + bb1);
        }
    }
}

// ---------------------------------------------------------------------------
// Node kernel (FFMA2): h += relu([h, agg] @ w1 + b1) @ w2 + b2; zero agg after
// ---------------------------------------------------------------------------
__global__ __launch_bounds__(256, 2)
void node_kernel(const float* __restrict__ w1, const float* __restrict__ b1,
                 const float* __restrict__ w2, const float* __restrict__ b2) {
    extern __shared__ float smemf[];
    float* As = smemf;
    float* Hs = smemf;

    const int tid = threadIdx.x;
    const int n0 = blockIdx.x * TE;

    {
        int r = tid >> 2;
        int p = tid & 3;
        int node = n0 + r;
        int cn = node < N_NODES ? node : (N_NODES - 1);
        const float4* gp = (p < 2)
            ? (const float4*)&g_h[(size_t)cn * H + p * 64]
            : (const float4*)&g_agg[(size_t)cn * H + (p - 2) * 64];
        float4* ap = (float4*)&As[r * AS_STRIDE + p * 64];
#pragma unroll
        for (int j = 0; j < 16; j++) ap[j] = gp[j];
        if (p >= 2 && node < N_NODES) {
            float4* zp = (float4*)&g_agg[(size_t)node * H + (p - 2) * 64];
            float4 z = make_float4(0.f, 0.f, 0.f, 0.f);
#pragma unroll
            for (int j = 0; j < 16; j++) zp[j] = z;
        }
    }
    __syncthreads();

    const int ty = tid >> 4;
    const int tx = tid & 15;
    const int erow = ty * 4;
    const int c0 = tx * 8;

    u64 acc[4][4];
#pragma unroll
    for (int j = 0; j < 4; j++) {
        u64 bj = pack2(b1[c0 + 2 * j], b1[c0 + 2 * j + 1]);
#pragma unroll
        for (int i = 0; i < 4; i++) acc[i][j] = bj;
    }

#pragma unroll 4
    for (int k = 0; k < 2 * H; k++) {
        u64 a0 = bcast2(As[(erow + 0) * AS_STRIDE + k]);
        u64 a1 = bcast2(As[(erow + 1) * AS_STRIDE + k]);
        u64 a2 = bcast2(As[(erow + 2) * AS_STRIDE + k]);
        u64 a3 = bcast2(As[(erow + 3) * AS_STRIDE + k]);
        ulonglong2 wl = __ldg((const ulonglong2*)&w1[k * H + c0]);
        ulonglong2 wh = __ldg((const ulonglong2*)&w1[k * H + c0 + 4]);
        u64 wp[4] = {wl.x, wl.y, wh.x, wh.y};
#pragma unroll
        for (int j = 0; j < 4; j++) {
            ffma2(acc[0][j], a0, wp[j]);
            ffma2(acc[1][j], a1, wp[j]);
            ffma2(acc[2][j], a2, wp[j]);
            ffma2(acc[3][j], a3, wp[j]);
        }
    }

    __syncthreads();
#pragma unroll
    for (int i = 0; i < 4; i++)
#pragma unroll
        for (int j = 0; j < 4; j++) {
            float2 v = unpk(acc[i][j]);
            Hs[(erow + i) * HS_STRIDE + c0 + 2 * j]     = fmaxf(v.x, 0.0f);
            Hs[(erow + i) * HS_STRIDE + c0 + 2 * j + 1] = fmaxf(v.y, 0.0f);
        }
    __syncthreads();

    u64 acc2[4][4];
#pragma unroll
    for (int j = 0; j < 4; j++) {
        u64 bj = pack2(b2[c0 + 2 * j], b2[c0 + 2 * j + 1]);
#pragma unroll
        for (int i = 0; i < 4; i++) acc2[i][j] = bj;
    }

#pragma unroll 4
    for (int k = 0; k < H; k++) {
        u64 a0 = bcast2(Hs[(erow + 0) * HS_STRIDE + k]);
        u64 a1 = bcast2(Hs[(erow + 1) * HS_STRIDE + k]);
        u64 a2 = bcast2(Hs[(erow + 2) * HS_STRIDE + k]);
        u64 a3 = bcast2(Hs[(erow + 3) * HS_STRIDE + k]);
        ulonglong2 wl = __ldg((const ulonglong2*)&w2[k * H + c0]);
        ulonglong2 wh = __ldg((const ulonglong2*)&w2[k * H + c0 + 4]);
        u64 wp[4] = {wl.x, wl.y, wh.x, wh.y};
#pragma unroll
        for (int j = 0; j < 4; j++) {
            ffma2(acc2[0][j], a0, wp[j]);
            ffma2(acc2[1][j], a1, wp[j]);
            ffma2(acc2[2][j], a2, wp[j]);
            ffma2(acc2[3][j], a3, wp[j]);
        }
    }

#pragma unroll
    for (int i = 0; i < 4; i++) {
        int node = n0 + erow + i;
        if (node < N_NODES) {
            float* hp = &g_h[(size_t)node * H + c0];
#pragma unroll
            for (int j = 0; j < 4; j++) {
                float2 v = unpk(acc2[i][j]);
                hp[2 * j]     += v.x;
                hp[2 * j + 1] += v.y;
            }
        }
    }
}

// ---------------------------------------------------------------------------
// Decoder
// ---------------------------------------------------------------------------
__global__ void dec_kernel(const float* __restrict__ w,
                           const float* __restrict__ b,
                           float* __restrict__ out) {
    int idx = blockIdx.x * blockDim.x + threadIdx.x;
    if (idx >= N_NODES * NODE_OUT) return;
    int node = idx / NODE_OUT;
    int j = idx - node * NODE_OUT;
    float acc = b[j];
    const float* hp = &g_h[(size_t)node * H];
#pragma unroll 8
    for (int k = 0; k < H; k++)
        acc = fmaf(hp[k], w[k * NODE_OUT + j], acc);
    out[idx] = acc;
}

// ---------------------------------------------------------------------------
extern "C" void kernel_launch(void* const* d_in, const int* in_sizes, int n_in,
                              void* d_out, int out_size) {
    const float* x      = (const float*)d_in[0];
    const void*  ei     = d_in[1];
    const float* enc_w  = (const float*)d_in[2];
    const float* enc_b  = (const float*)d_in[3];
    const float* dec_w  = (const float*)d_in[4];
    const float* dec_b  = (const float*)d_in[5];
    const float* e_w1   = (const float*)d_in[6];
    const float* e_b1   = (const float*)d_in[7];
    const float* e_w2   = (const float*)d_in[8];
    const float* e_b2   = (const float*)d_in[9];
    const float* n_w1   = (const float*)d_in[10];
    const float* n_b1   = (const float*)d_in[11];
    const float* n_w2   = (const float*)d_in[12];
    const float* n_b2   = (const float*)d_in[13];
    float*       out    = (float*)d_out;

    const size_t node_smem = (size_t)(TE * AS_STRIDE) * sizeof(float);
    static int attr_set = 0;
    if (!attr_set) {
        cudaFuncSetAttribute(node_kernel, cudaFuncAttributeMaxDynamicSharedMemorySize,
                             (int)node_smem);
        cudaFuncSetAttribute(edge_kernel_mma, cudaFuncAttributeMaxDynamicSharedMemorySize,
                             EDGE_SMEM);
        attr_set = 1;
    }

    detect_kernel<<<1, 32>>>(ei);
    convert_kernel<<<(2 * N_EDGES + 255) / 256, 256>>>(ei);
    prep_w_kernel<<<(N_LAYERS * (2 * H * H + H * H) + 255) / 256, 256>>>(e_w1, e_w2);
    enc_kernel<<<(N_NODES * H + 255) / 256, 256>>>(x, enc_w, enc_b);

    for (int l = 0; l < N_LAYERS; l++) {
        edge_kernel_mma<<<N_EDGES / ET, 256, EDGE_SMEM>>>(
            e_b1 + (size_t)l * H, e_b2 + (size_t)l * H, l);
        node_kernel<<<(N_NODES + TE - 1) / TE, 256, node_smem>>>(
            n_w1 + (size_t)l * 2 * H * H, n_b1 + (size_t)l * H,
            n_w2 + (size_t)l * H * H,     n_b2 + (size_t)l * H);
    }

    dec_kernel<<<(N_NODES * NODE_OUT + 255) / 256, 256>>>(dec_w, dec_b, out);
}

// round 8
// speedup vs baseline: 2.8291x; 1.7866x over previous
#include <cuda_runtime.h>
#include <cuda_bf16.h>
#include <cstdint>

#define N_NODES 50000
#define N_EDGES 800000
#define NODE_IN 16
#define NODE_OUT 3
#define H 128
#define N_LAYERS 3

// ---- FFMA2 node-kernel tile params
#define TE 64
#define AS_STRIDE 260
#define HS_STRIDE 132

// ---- mma edge-kernel params
#define ET 128                       // edges per block tile
// smem byte offsets (dynamic) — A2 overlays A1 (A1 dead after GEMM1)
#define A2H_OFF 0                    // [128][136] bf16 = 34816 B
#define A2L_OFF 34816
#define A1H_OFF 0                    // [128][72] bf16 = 18432 B (inside A2H)
#define A1L_OFF 34816                // (inside A2L)
#define BH_OFF  69632                // [128][72] bf16
#define BL_OFF  88064
#define EDGE_SMEM 106496             // fits 2 CTAs/SM
#define SA1 72                       // bf16 units per row (64 + 8 pad)
#define SB  72
#define SA2 136                      // 128 + 8 pad

typedef unsigned long long u64;

// ---------------------------------------------------------------------------
// Scratch (__device__ globals; alloc-free rule)
// ---------------------------------------------------------------------------
__device__ float g_h[N_NODES * H];
__device__ float g_agg[N_NODES * H];
__device__ int   g_src[N_EDGES];
__device__ int   g_dst[N_EDGES];
__device__ int   g_is64;
// transposed hi/lo-split bf16 edge weights: w^T indexed [c][k]
__device__ __nv_bfloat16 g_w1t[N_LAYERS][2][H][2 * H];
__device__ __nv_bfloat16 g_w2t[N_LAYERS][2][H][H];

// ---------------------------------------------------------------------------
// helpers
// ---------------------------------------------------------------------------
__device__ __forceinline__ uint32_t smem_u32(const void* p) {
    uint32_t a;
    asm("{ .reg .u64 t; cvta.to.shared.u64 t, %1; cvt.u32.u64 %0, t; }"
        : "=r"(a) : "l"(p));
    return a;
}
__device__ __forceinline__ void ldm_x4(uint32_t* r, uint32_t addr) {
    asm volatile("ldmatrix.sync.aligned.m8n8.x4.shared.b16 {%0,%1,%2,%3}, [%4];"
                 : "=r"(r[0]), "=r"(r[1]), "=r"(r[2]), "=r"(r[3]) : "r"(addr));
}
__device__ __forceinline__ void mma_bf16(float* c, const uint32_t* a, const uint32_t* b) {
    asm volatile(
        "mma.sync.aligned.m16n8k16.row.col.f32.bf16.bf16.f32 "
        "{%0,%1,%2,%3}, {%4,%5,%6,%7}, {%8,%9}, {%0,%1,%2,%3};"
        : "+f"(c[0]), "+f"(c[1]), "+f"(c[2]), "+f"(c[3])
        : "r"(a[0]), "r"(a[1]), "r"(a[2]), "r"(a[3]), "r"(b[0]), "r"(b[1]));
}
__device__ __forceinline__ void split2(float a, float b, uint32_t& hi, uint32_t& lo) {
    __nv_bfloat16 ha = __float2bfloat16(a), hb = __float2bfloat16(b);
    hi = (uint32_t)__bfloat16_as_ushort(ha) | ((uint32_t)__bfloat16_as_ushort(hb) << 16);
    __nv_bfloat16 la = __float2bfloat16(a - __bfloat162float(ha));
    __nv_bfloat16 lb = __float2bfloat16(b - __bfloat162float(hb));
    lo = (uint32_t)__bfloat16_as_ushort(la) | ((uint32_t)__bfloat16_as_ushort(lb) << 16);
}
__device__ __forceinline__ void red_add_v2(float* p, float a, float b) {
    asm volatile("red.global.add.v2.f32 [%0], {%1, %2};"
                 :: "l"(p), "f"(a), "f"(b) : "memory");
}
// ---- FFMA2 helpers (node kernel)
__device__ __forceinline__ u64 pack2(float lo, float hi) {
    u64 r; asm("mov.b64 %0, {%1, %2};" : "=l"(r) : "f"(lo), "f"(hi)); return r;
}
__device__ __forceinline__ u64 bcast2(float v) { return pack2(v, v); }
__device__ __forceinline__ void ffma2(u64& d, u64 a, u64 b) {
    asm("fma.rn.f32x2 %0, %1, %2, %0;" : "+l"(d) : "l"(a), "l"(b));
}
__device__ __forceinline__ float2 unpk(u64 v) {
    float2 f; asm("mov.b64 {%0, %1}, %2;" : "=f"(f.x), "=f"(f.y) : "l"(v)); return f;
}

// ---------------------------------------------------------------------------
// dtype probe + convert
// ---------------------------------------------------------------------------
__global__ void detect_kernel(const void* __restrict__ ei) {
    if (threadIdx.x == 0 && blockIdx.x == 0) {
        const long long* p = (const long long*)ei;
        int is64 = 1;
        for (int i = 0; i < 256; i++) {
            long long v = p[i];
            if (v < 0 || v >= N_NODES) { is64 = 0; break; }
        }
        g_is64 = is64;
    }
}

__global__ void convert_kernel(const void* __restrict__ ei) {
    int i = blockIdx.x * blockDim.x + threadIdx.x;
    if (i >= 2 * N_EDGES) return;
    int v;
    if (g_is64) v = (int)((const long long*)ei)[i];
    else        v = ((const int*)ei)[i];
    if (i < N_EDGES) g_src[i] = v;
    else             g_dst[i - N_EDGES] = v;
}

// ---------------------------------------------------------------------------
// Weight prep: transposed hi/lo-split bf16 edge weights (w^T [c][k])
// ---------------------------------------------------------------------------
__global__ void prep_w_kernel(const float* __restrict__ e_w1,
                              const float* __restrict__ e_w2) {
    int idx = blockIdx.x * blockDim.x + threadIdx.x;
    const int W1E = N_LAYERS * 2 * H * H;
    const int W2E = N_LAYERS * H * H;
    if (idx < W1E) {
        int l = idx / (2 * H * H);
        int rem = idx % (2 * H * H);
        int k = rem / H, c = rem % H;
        float w = e_w1[idx];
        __nv_bfloat16 hi = __float2bfloat16(w);
        __nv_bfloat16 lo = __float2bfloat16(w - __bfloat162float(hi));
        g_w1t[l][0][c][k] = hi;
        g_w1t[l][1][c][k] = lo;
    } else if (idx < W1E + W2E) {
        int j = idx - W1E;
        int l = j / (H * H);
        int rem = j % (H * H);
        int k = rem / H, c = rem % H;
        float w = e_w2[j];
        __nv_bfloat16 hi = __float2bfloat16(w);
        __nv_bfloat16 lo = __float2bfloat16(w - __bfloat162float(hi));
        g_w2t[l][0][c][k] = hi;
        g_w2t[l][1][c][k] = lo;
    }
}

// ---------------------------------------------------------------------------
// Encoder (+ zero g_agg)
// ---------------------------------------------------------------------------
__global__ void enc_kernel(const float* __restrict__ x,
                           const float* __restrict__ w,
                           const float* __restrict__ b) {
    int idx = blockIdx.x * blockDim.x + threadIdx.x;
    if (idx >= N_NODES * H) return;
    int node = idx >> 7;
    int c = idx & (H - 1);
    float acc = b[c];
#pragma unroll
    for (int k = 0; k < NODE_IN; k++)
        acc = fmaf(x[node * NODE_IN + k], w[k * H + c], acc);
    g_h[idx] = acc;
    g_agg[idx] = 0.0f;
}

// ---------------------------------------------------------------------------
// mma chunk: C += A(hi/lo)[rows r0..+31][k 0..63] x B^T cols c0w..+63 (3-pass)
// ---------------------------------------------------------------------------
__device__ __forceinline__ void mma_chunk(
    uint32_t a_hi, uint32_t a_lo, int astride,
    uint32_t b_hi, uint32_t b_lo,
    float C[2][8][4], int r0, int c0w, int lane)
{
    const int arow = lane & 15;
    const int acol = (lane >> 4) * 8;
    const int brow = (lane & 7) + ((lane >> 4) << 3);
    const int bcol = ((lane >> 3) & 1) * 8;
#pragma unroll
    for (int ks = 0; ks < 4; ks++) {
        uint32_t ah[2][4], al[2][4], bh[4][4], bl[4][4];
#pragma unroll
        for (int i = 0; i < 2; i++) {
            uint32_t off = (uint32_t)(((r0 + i * 16 + arow) * astride + ks * 16 + acol) * 2);
            ldm_x4(ah[i], a_hi + off);
            ldm_x4(al[i], a_lo + off);
        }
#pragma unroll
        for (int p = 0; p < 4; p++) {
            uint32_t off = (uint32_t)(((c0w + p * 16 + brow) * SB + ks * 16 + bcol) * 2);
            ldm_x4(bh[p], b_hi + off);
            ldm_x4(bl[p], b_lo + off);
        }
#pragma unroll
        for (int i = 0; i < 2; i++)
#pragma unroll
            for (int p = 0; p < 4; p++) {
                mma_bf16(C[i][2 * p],     ah[i], &bh[p][0]);
                mma_bf16(C[i][2 * p],     ah[i], &bl[p][0]);
                mma_bf16(C[i][2 * p],     al[i], &bh[p][0]);
                mma_bf16(C[i][2 * p + 1], ah[i], &bh[p][2]);
                mma_bf16(C[i][2 * p + 1], ah[i], &bl[p][2]);
                mma_bf16(C[i][2 * p + 1], al[i], &bh[p][2]);
            }
    }
}

// ---------------------------------------------------------------------------
// Edge kernel (tensor-core mma.sync): 128 edges/block, 8 warps, 2 CTAs/SM
// ---------------------------------------------------------------------------
__global__ __launch_bounds__(256, 2)
void edge_kernel_mma(const float* __restrict__ b1,
                     const float* __restrict__ b2, int layer) {
    extern __shared__ char smem[];
    const uint32_t sbase = smem_u32(smem);
    const int tid = threadIdx.x;
    const int lane = tid & 31;
    const int wid = tid >> 5;
    const int e0 = blockIdx.x * ET;

    // staging role: 2 threads per row
    const int srow = tid >> 1;
    const int shalf = tid & 1;
    const int ssrc = g_src[e0 + srow];
    const int sdst = g_dst[e0 + srow];

    // warp tile: rows r0..r0+31, cols c0w..c0w+63
    const int r0 = (wid >> 1) * 32;
    const int c0w = (wid & 1) * 64;

    float C[2][8][4];
#pragma unroll
    for (int i = 0; i < 2; i++)
#pragma unroll
        for (int j = 0; j < 8; j++)
#pragma unroll
            for (int q = 0; q < 4; q++) C[i][j][q] = 0.0f;

    // ================= GEMM1: K=256 in 4 chunks of 64 =================
    for (int kc = 0; kc < 4; kc++) {
        // stage A chunk: gather + hi/lo split
        {
            int node = (kc < 2) ? ssrc : sdst;
            const float4* hp = (const float4*)&g_h[(size_t)node * H + (kc & 1) * 64 + shalf * 32];
            uint32_t ph[16], pl[16];
#pragma unroll
            for (int i = 0; i < 8; i++) {
                float4 v = hp[i];
                split2(v.x, v.y, ph[2 * i],     pl[2 * i]);
                split2(v.z, v.w, ph[2 * i + 1], pl[2 * i + 1]);
            }
            uint4* dh = (uint4*)(smem + A1H_OFF + srow * (SA1 * 2) + shalf * 64);
            uint4* dl = (uint4*)(smem + A1L_OFF + srow * (SA1 * 2) + shalf * 64);
#pragma unroll
            for (int i = 0; i < 4; i++) {
                dh[i] = make_uint4(ph[4 * i], ph[4 * i + 1], ph[4 * i + 2], ph[4 * i + 3]);
                dl[i] = make_uint4(pl[4 * i], pl[4 * i + 1], pl[4 * i + 2], pl[4 * i + 3]);
            }
        }
        // stage B chunk: w1t[c][kc*64 + ...]
        {
            const float4* sh = (const float4*)&g_w1t[layer][0][srow][kc * 64 + shalf * 32];
            const float4* sl = (const float4*)&g_w1t[layer][1][srow][kc * 64 + shalf * 32];
            float4* dh = (float4*)(smem + BH_OFF + srow * (SB * 2) + shalf * 64);
            float4* dl = (float4*)(smem + BL_OFF + srow * (SB * 2) + shalf * 64);
#pragma unroll
            for (int i = 0; i < 4; i++) { dh[i] = sh[i]; dl[i] = sl[i]; }
        }
        __syncthreads();
        mma_chunk(sbase + A1H_OFF, sbase + A1L_OFF, SA1,
                  sbase + BH_OFF, sbase + BL_OFF, C, r0, c0w, lane);
        __syncthreads();
    }

    // ================= Epilogue1: bias + relu + resplit into A2 =================
#pragma unroll
    for (int i = 0; i < 2; i++)
#pragma unroll
        for (int j = 0; j < 8; j++) {
            int col = c0w + j * 8 + (lane & 3) * 2;
            int row = r0 + i * 16 + (lane >> 2);
            float bb0 = b1[col], bb1 = b1[col + 1];
            uint32_t hi, lo;
            split2(fmaxf(C[i][j][0] + bb0, 0.0f), fmaxf(C[i][j][1] + bb1, 0.0f), hi, lo);
            *(uint32_t*)(smem + A2H_OFF + row * (SA2 * 2) + col * 2) = hi;
            *(uint32_t*)(smem + A2L_OFF + row * (SA2 * 2) + col * 2) = lo;
            split2(fmaxf(C[i][j][2] + bb0, 0.0f), fmaxf(C[i][j][3] + bb1, 0.0f), hi, lo);
            *(uint32_t*)(smem + A2H_OFF + (row + 8) * (SA2 * 2) + col * 2) = hi;
            *(uint32_t*)(smem + A2L_OFF + (row + 8) * (SA2 * 2) + col * 2) = lo;
        }
    __syncthreads();

    // ================= GEMM2: K=128 in 2 chunks =================
#pragma unroll
    for (int i = 0; i < 2; i++)
#pragma unroll
        for (int j = 0; j < 8; j++)
#pragma unroll
            for (int q = 0; q < 4; q++) C[i][j][q] = 0.0f;

    for (int kc = 0; kc < 2; kc++) {
        {
            const float4* sh = (const float4*)&g_w2t[layer][0][srow][kc * 64 + shalf * 32];
            const float4* sl = (const float4*)&g_w2t[layer][1][srow][kc * 64 + shalf * 32];
            float4* dh = (float4*)(smem + BH_OFF + srow * (SB * 2) + shalf * 64);
            float4* dl = (float4*)(smem + BL_OFF + srow * (SB * 2) + shalf * 64);
#pragma unroll
            for (int i = 0; i < 4; i++) { dh[i] = sh[i]; dl[i] = sl[i]; }
        }
        __syncthreads();
        mma_chunk(sbase + A2H_OFF + kc * 128, sbase + A2L_OFF + kc * 128, SA2,
                  sbase + BH_OFF, sbase + BL_OFF, C, r0, c0w, lane);
        __syncthreads();
    }

    // ================= Epilogue2: bias + scatter-add =================
#pragma unroll
    for (int i = 0; i < 2; i++) {
        int row = r0 + i * 16 + (lane >> 2);
        int d0 = g_dst[e0 + row];
        int d1 = g_dst[e0 + row + 8];
#pragma unroll
        for (int j = 0; j < 8; j++) {
            int col = c0w + j * 8 + (lane & 3) * 2;
            float bb0 = b2[col], bb1 = b2[col + 1];
            red_add_v2(&g_agg[(size_t)d0 * H + col], C[i][j][0] + bb0, C[i][j][1] + bb1);
            red_add_v2(&g_agg[(size_t)d1 * H + col], C[i][j][2] + bb0, C[i][j][3] + bb1);
        }
    }
}

// ---------------------------------------------------------------------------
// Node kernel (FFMA2): h += relu([h, agg] @ w1 + b1) @ w2 + b2; zero agg after
// ---------------------------------------------------------------------------
__global__ __launch_bounds__(256, 2)
void node_kernel(const float* __restrict__ w1, const float* __restrict__ b1,
                 const float* __restrict__ w2, const float* __restrict__ b2) {
    extern __shared__ float smemf[];
    float* As = smemf;
    float* Hs = smemf;

    const int tid = threadIdx.x;
    const int n0 = blockIdx.x * TE;

    {
        int r = tid >> 2;
        int p = tid & 3;
        int node = n0 + r;
        int cn = node < N_NODES ? node : (N_NODES - 1);
        const float4* gp = (p < 2)
            ? (const float4*)&g_h[(size_t)cn * H + p * 64]
            : (const float4*)&g_agg[(size_t)cn * H + (p - 2) * 64];
        float4* ap = (float4*)&As[r * AS_STRIDE + p * 64];
#pragma unroll
        for (int j = 0; j < 16; j++) ap[j] = gp[j];
        if (p >= 2 && node < N_NODES) {
            float4* zp = (float4*)&g_agg[(size_t)node * H + (p - 2) * 64];
            float4 z = make_float4(0.f, 0.f, 0.f, 0.f);
#pragma unroll
            for (int j = 0; j < 16; j++) zp[j] = z;
        }
    }
    __syncthreads();

    const int ty = tid >> 4;
    const int tx = tid & 15;
    const int erow = ty * 4;
    const int c0 = tx * 8;

    u64 acc[4][4];
#pragma unroll
    for (int j = 0; j < 4; j++) {
        u64 bj = pack2(b1[c0 + 2 * j], b1[c0 + 2 * j + 1]);
#pragma unroll
        for (int i = 0; i < 4; i++) acc[i][j] = bj;
    }

#pragma unroll 4
    for (int k = 0; k < 2 * H; k++) {
        u64 a0 = bcast2(As[(erow + 0) * AS_STRIDE + k]);
        u64 a1 = bcast2(As[(erow + 1) * AS_STRIDE + k]);
        u64 a2 = bcast2(As[(erow + 2) * AS_STRIDE + k]);
        u64 a3 = bcast2(As[(erow + 3) * AS_STRIDE + k]);
        ulonglong2 wl = __ldg((const ulonglong2*)&w1[k * H + c0]);
        ulonglong2 wh = __ldg((const ulonglong2*)&w1[k * H + c0 + 4]);
        u64 wp[4] = {wl.x, wl.y, wh.x, wh.y};
#pragma unroll
        for (int j = 0; j < 4; j++) {
            ffma2(acc[0][j], a0, wp[j]);
            ffma2(acc[1][j], a1, wp[j]);
            ffma2(acc[2][j], a2, wp[j]);
            ffma2(acc[3][j], a3, wp[j]);
        }
    }

    __syncthreads();
#pragma unroll
    for (int i = 0; i < 4; i++)
#pragma unroll
        for (int j = 0; j < 4; j++) {
            float2 v = unpk(acc[i][j]);
            Hs[(erow + i) * HS_STRIDE + c0 + 2 * j]     = fmaxf(v.x, 0.0f);
            Hs[(erow + i) * HS_STRIDE + c0 + 2 * j + 1] = fmaxf(v.y, 0.0f);
        }
    __syncthreads();

    u64 acc2[4][4];
#pragma unroll
    for (int j = 0; j < 4; j++) {
        u64 bj = pack2(b2[c0 + 2 * j], b2[c0 + 2 * j + 1]);
#pragma unroll
        for (int i = 0; i < 4; i++) acc2[i][j] = bj;
    }

#pragma unroll 4
    for (int k = 0; k < H; k++) {
        u64 a0 = bcast2(Hs[(erow + 0) * HS_STRIDE + k]);
        u64 a1 = bcast2(Hs[(erow + 1) * HS_STRIDE + k]);
        u64 a2 = bcast2(Hs[(erow + 2) * HS_STRIDE + k]);
        u64 a3 = bcast2(Hs[(erow + 3) * HS_STRIDE + k]);
        ulonglong2 wl = __ldg((const ulonglong2*)&w2[k * H + c0]);
        ulonglong2 wh = __ldg((const ulonglong2*)&w2[k * H + c0 + 4]);
        u64 wp[4] = {wl.x, wl.y, wh.x, wh.y};
#pragma unroll
        for (int j = 0; j < 4; j++) {
            ffma2(acc2[0][j], a0, wp[j]);
            ffma2(acc2[1][j], a1, wp[j]);
            ffma2(acc2[2][j], a2, wp[j]);
            ffma2(acc2[3][j], a3, wp[j]);
        }
    }

#pragma unroll
    for (int i = 0; i < 4; i++) {
        int node = n0 + erow + i;
        if (node < N_NODES) {
            float* hp = &g_h[(size_t)node * H + c0];
#pragma unroll
            for (int j = 0; j < 4; j++) {
                float2 v = unpk(acc2[i][j]);
                hp[2 * j]     += v.x;
                hp[2 * j + 1] += v.y;
            }
        }
    }
}

// ---------------------------------------------------------------------------
// Decoder
// ---------------------------------------------------------------------------
__global__ void dec_kernel(const float* __restrict__ w,
                           const float* __restrict__ b,
                           float* __restrict__ out) {
    int idx = blockIdx.x * blockDim.x + threadIdx.x;
    if (idx >= N_NODES * NODE_OUT) return;
    int node = idx / NODE_OUT;
    int j = idx - node * NODE_OUT;
    float acc = b[j];
    const float* hp = &g_h[(size_t)node * H];
#pragma unroll 8
    for (int k = 0; k < H; k++)
        acc = fmaf(hp[k], w[k * NODE_OUT + j], acc);
    out[idx] = acc;
}

// ---------------------------------------------------------------------------
extern "C" void kernel_launch(void* const* d_in, const int* in_sizes, int n_in,
                              void* d_out, int out_size) {
    const float* x      = (const float*)d_in[0];
    const void*  ei     = d_in[1];
    const float* enc_w  = (const float*)d_in[2];
    const float* enc_b  = (const float*)d_in[3];
    const float* dec_w  = (const float*)d_in[4];
    const float* dec_b  = (const float*)d_in[5];
    const float* e_w1   = (const float*)d_in[6];
    const float* e_b1   = (const float*)d_in[7];
    const float* e_w2   = (const float*)d_in[8];
    const float* e_b2   = (const float*)d_in[9];
    const float* n_w1   = (const float*)d_in[10];
    const float* n_b1   = (const float*)d_in[11];
    const float* n_w2   = (const float*)d_in[12];
    const float* n_b2   = (const float*)d_in[13];
    float*       out    = (float*)d_out;

    const size_t node_smem = (size_t)(TE * AS_STRIDE) * sizeof(float);
    static int attr_set = 0;
    if (!attr_set) {
        cudaFuncSetAttribute(node_kernel, cudaFuncAttributeMaxDynamicSharedMemorySize,
                             (int)node_smem);
        cudaFuncSetAttribute(edge_kernel_mma, cudaFuncAttributeMaxDynamicSharedMemorySize,
                             EDGE_SMEM);
        attr_set = 1;
    }

    detect_kernel<<<1, 32>>>(ei);
    convert_kernel<<<(2 * N_EDGES + 255) / 256, 256>>>(ei);
    prep_w_kernel<<<(N_LAYERS * (2 * H * H + H * H) + 255) / 256, 256>>>(e_w1, e_w2);
    enc_kernel<<<(N_NODES * H + 255) / 256, 256>>>(x, enc_w, enc_b);

    for (int l = 0; l < N_LAYERS; l++) {
        edge_kernel_mma<<<N_EDGES / ET, 256, EDGE_SMEM>>>(
            e_b1 + (size_t)l * H, e_b2 + (size_t)l * H, l);
        node_kernel<<<(N_NODES + TE - 1) / TE, 256, node_smem>>>(
            n_w1 + (size_t)l * 2 * H * H, n_b1 + (size_t)l * H,
            n_w2 + (size_t)l * H * H,     n_b2 + (size_t)l * H);
    }

    dec_kernel<<<(N_NODES * NODE_OUT + 255) / 256, 256>>>(dec_w, dec_b, out);
}

// round 10
// speedup vs baseline: 3.1695x; 1.1203x over previous
#include <cuda_runtime.h>
#include <cuda_bf16.h>
#include <cstdint>

#define N_NODES 50000
#define N_EDGES 800000
#define NODE_IN 16
#define NODE_OUT 3
#define H 128
#define N_LAYERS 3

// ---- mma kernel params (shared by edge + node kernels)
#define ET 128                       // rows per block tile
// smem byte offsets (dynamic) — A2 overlays A1 (A1 dead after GEMM1)
#define A2H_OFF 0                    // [128][136] bf16 = 34816 B
#define A2L_OFF 34816
#define A1H_OFF 0                    // [128][72] bf16 = 18432 B (inside A2H)
#define A1L_OFF 34816                // (inside A2L)
#define BH_OFF  69632                // [128][72] bf16
#define BL_OFF  88064
#define EDGE_SMEM 106496             // fits 2 CTAs/SM
#define SA1 72                       // bf16 units per row (64 + 8 pad)
#define SB  72
#define SA2 136                      // 128 + 8 pad

typedef unsigned long long u64;

// ---------------------------------------------------------------------------
// Scratch (__device__ globals; alloc-free rule)
// ---------------------------------------------------------------------------
__device__ float g_h[N_NODES * H];
__device__ float g_agg[N_NODES * H];
__device__ int   g_src[N_EDGES];
__device__ int   g_dst[N_EDGES];
__device__ int   g_is64;
// transposed hi/lo-split bf16 weights: w^T indexed [c][k]
__device__ __nv_bfloat16 g_ew1t[N_LAYERS][2][H][2 * H];
__device__ __nv_bfloat16 g_ew2t[N_LAYERS][2][H][H];
__device__ __nv_bfloat16 g_nw1t[N_LAYERS][2][H][2 * H];
__device__ __nv_bfloat16 g_nw2t[N_LAYERS][2][H][H];

// ---------------------------------------------------------------------------
// helpers
// ---------------------------------------------------------------------------
__device__ __forceinline__ uint32_t smem_u32(const void* p) {
    uint32_t a;
    asm("{ .reg .u64 t; cvta.to.shared.u64 t, %1; cvt.u32.u64 %0, t; }"
        : "=r"(a) : "l"(p));
    return a;
}
__device__ __forceinline__ void ldm_x4(uint32_t* r, uint32_t addr) {
    asm volatile("ldmatrix.sync.aligned.m8n8.x4.shared.b16 {%0,%1,%2,%3}, [%4];"
                 : "=r"(r[0]), "=r"(r[1]), "=r"(r[2]), "=r"(r[3]) : "r"(addr));
}
__device__ __forceinline__ void mma_bf16(float* c, const uint32_t* a, const uint32_t* b) {
    asm volatile(
        "mma.sync.aligned.m16n8k16.row.col.f32.bf16.bf16.f32 "
        "{%0,%1,%2,%3}, {%4,%5,%6,%7}, {%8,%9}, {%0,%1,%2,%3};"
        : "+f"(c[0]), "+f"(c[1]), "+f"(c[2]), "+f"(c[3])
        : "r"(a[0]), "r"(a[1]), "r"(a[2]), "r"(a[3]), "r"(b[0]), "r"(b[1]));
}
__device__ __forceinline__ void split2(float a, float b, uint32_t& hi, uint32_t& lo) {
    __nv_bfloat16 ha = __float2bfloat16(a), hb = __float2bfloat16(b);
    hi = (uint32_t)__bfloat16_as_ushort(ha) | ((uint32_t)__bfloat16_as_ushort(hb) << 16);
    __nv_bfloat16 la = __float2bfloat16(a - __bfloat162float(ha));
    __nv_bfloat16 lb = __float2bfloat16(b - __bfloat162float(hb));
    lo = (uint32_t)__bfloat16_as_ushort(la) | ((uint32_t)__bfloat16_as_ushort(lb) << 16);
}
__device__ __forceinline__ void red_add_v2(float* p, float a, float b) {
    asm volatile("red.global.add.v2.f32 [%0], {%1, %2};"
                 :: "l"(p), "f"(a), "f"(b) : "memory");
}

// ---------------------------------------------------------------------------
// dtype probe + convert
// ---------------------------------------------------------------------------
__global__ void detect_kernel(const void* __restrict__ ei) {
    if (threadIdx.x == 0 && blockIdx.x == 0) {
        const long long* p = (const long long*)ei;
        int is64 = 1;
        for (int i = 0; i < 256; i++) {
            long long v = p[i];
            if (v < 0 || v >= N_NODES) { is64 = 0; break; }
        }
        g_is64 = is64;
    }
}

__global__ void convert_kernel(const void* __restrict__ ei) {
    int i = blockIdx.x * blockDim.x + threadIdx.x;
    if (i >= 2 * N_EDGES) return;
    int v;
    if (g_is64) v = (int)((const long long*)ei)[i];
    else        v = ((const int*)ei)[i];
    if (i < N_EDGES) g_src[i] = v;
    else             g_dst[i - N_EDGES] = v;
}

// ---------------------------------------------------------------------------
// Weight prep: transposed hi/lo-split bf16 (w^T [c][k]) for edge + node MLPs
// ---------------------------------------------------------------------------
__global__ void prep_w_kernel(const float* __restrict__ e_w1,
                              const float* __restrict__ e_w2,
                              const float* __restrict__ n_w1,
                              const float* __restrict__ n_w2) {
    int idx = blockIdx.x * blockDim.x + threadIdx.x;
    const int W1E = N_LAYERS * 2 * H * H;
    const int W2E = N_LAYERS * H * H;
    if (idx < 2 * (W1E + W2E)) {
        int which = idx >= (W1E + W2E);               // 0 = edge, 1 = node
        int j = idx - which * (W1E + W2E);
        if (j < W1E) {
            int l = j / (2 * H * H);
            int rem = j % (2 * H * H);
            int k = rem / H, c = rem % H;
            float w = which ? n_w1[j] : e_w1[j];
            __nv_bfloat16 hi = __float2bfloat16(w);
            __nv_bfloat16 lo = __float2bfloat16(w - __bfloat162float(hi));
            if (which) { g_nw1t[l][0][c][k] = hi; g_nw1t[l][1][c][k] = lo; }
            else       { g_ew1t[l][0][c][k] = hi; g_ew1t[l][1][c][k] = lo; }
        } else {
            int q = j - W1E;
            int l = q / (H * H);
            int rem = q % (H * H);
            int k = rem / H, c = rem % H;
            float w = which ? n_w2[q] : e_w2[q];
            __nv_bfloat16 hi = __float2bfloat16(w);
            __nv_bfloat16 lo = __float2bfloat16(w - __bfloat162float(hi));
            if (which) { g_nw2t[l][0][c][k] = hi; g_nw2t[l][1][c][k] = lo; }
            else       { g_ew2t[l][0][c][k] = hi; g_ew2t[l][1][c][k] = lo; }
        }
    }
}

// ---------------------------------------------------------------------------
// Encoder (+ zero g_agg)
// ---------------------------------------------------------------------------
__global__ void enc_kernel(const float* __restrict__ x,
                           const float* __restrict__ w,
                           const float* __restrict__ b) {
    int idx = blockIdx.x * blockDim.x + threadIdx.x;
    if (idx >= N_NODES * H) return;
    int node = idx >> 7;
    int c = idx & (H - 1);
    float acc = b[c];
#pragma unroll
    for (int k = 0; k < NODE_IN; k++)
        acc = fmaf(x[node * NODE_IN + k], w[k * H + c], acc);
    g_h[idx] = acc;
    g_agg[idx] = 0.0f;
}

// ---------------------------------------------------------------------------
// mma chunk: C += A(hi/lo)[rows r0..+31][k 0..63] x B^T cols c0w..+63 (3-pass)
// ---------------------------------------------------------------------------
__device__ __forceinline__ void mma_chunk(
    uint32_t a_hi, uint32_t a_lo, int astride,
    uint32_t b_hi, uint32_t b_lo,
    float C[2][8][4], int r0, int c0w, int lane)
{
    const int arow = lane & 15;
    const int acol = (lane >> 4) * 8;
    const int brow = (lane & 7) + ((lane >> 4) << 3);
    const int bcol = ((lane >> 3) & 1) * 8;
#pragma unroll
    for (int ks = 0; ks < 4; ks++) {
        uint32_t ah[2][4], al[2][4], bh[4][4], bl[4][4];
#pragma unroll
        for (int i = 0; i < 2; i++) {
            uint32_t off = (uint32_t)(((r0 + i * 16 + arow) * astride + ks * 16 + acol) * 2);
            ldm_x4(ah[i], a_hi + off);
            ldm_x4(al[i], a_lo + off);
        }
#pragma unroll
        for (int p = 0; p < 4; p++) {
            uint32_t off = (uint32_t)(((c0w + p * 16 + brow) * SB + ks * 16 + bcol) * 2);
            ldm_x4(bh[p], b_hi + off);
            ldm_x4(bl[p], b_lo + off);
        }
#pragma unroll
        for (int i = 0; i < 2; i++)
#pragma unroll
            for (int p = 0; p < 4; p++) {
                mma_bf16(C[i][2 * p],     ah[i], &bh[p][0]);
                mma_bf16(C[i][2 * p],     ah[i], &bl[p][0]);
                mma_bf16(C[i][2 * p],     al[i], &bh[p][0]);
                mma_bf16(C[i][2 * p + 1], ah[i], &bh[p][2]);
                mma_bf16(C[i][2 * p + 1], ah[i], &bl[p][2]);
                mma_bf16(C[i][2 * p + 1], al[i], &bh[p][2]);
            }
    }
}

// ---------------------------------------------------------------------------
// Edge kernel (tensor-core mma.sync): 128 edges/block, 8 warps, 2 CTAs/SM
// ---------------------------------------------------------------------------
__global__ __launch_bounds__(256, 2)
void edge_kernel_mma(const float* __restrict__ b1,
                     const float* __restrict__ b2, int layer) {
    extern __shared__ char smem[];
    const uint32_t sbase = smem_u32(smem);
    const int tid = threadIdx.x;
    const int lane = tid & 31;
    const int wid = tid >> 5;
    const int e0 = blockIdx.x * ET;

    const int srow = tid >> 1;
    const int shalf = tid & 1;
    const int ssrc = g_src[e0 + srow];
    const int sdst = g_dst[e0 + srow];

    const int r0 = (wid >> 1) * 32;
    const int c0w = (wid & 1) * 64;

    float C[2][8][4];
#pragma unroll
    for (int i = 0; i < 2; i++)
#pragma unroll
        for (int j = 0; j < 8; j++)
#pragma unroll
            for (int q = 0; q < 4; q++) C[i][j][q] = 0.0f;

    // ================= GEMM1: K=256 in 4 chunks of 64 =================
    for (int kc = 0; kc < 4; kc++) {
        {
            int node = (kc < 2) ? ssrc : sdst;
            const float4* hp = (const float4*)&g_h[(size_t)node * H + (kc & 1) * 64 + shalf * 32];
            uint32_t ph[16], pl[16];
#pragma unroll
            for (int i = 0; i < 8; i++) {
                float4 v = hp[i];
                split2(v.x, v.y, ph[2 * i],     pl[2 * i]);
                split2(v.z, v.w, ph[2 * i + 1], pl[2 * i + 1]);
            }
            uint4* dh = (uint4*)(smem + A1H_OFF + srow * (SA1 * 2) + shalf * 64);
            uint4* dl = (uint4*)(smem + A1L_OFF + srow * (SA1 * 2) + shalf * 64);
#pragma unroll
            for (int i = 0; i < 4; i++) {
                dh[i] = make_uint4(ph[4 * i], ph[4 * i + 1], ph[4 * i + 2], ph[4 * i + 3]);
                dl[i] = make_uint4(pl[4 * i], pl[4 * i + 1], pl[4 * i + 2], pl[4 * i + 3]);
            }
        }
        {
            const float4* sh = (const float4*)&g_ew1t[layer][0][srow][kc * 64 + shalf * 32];
            const float4* sl = (const float4*)&g_ew1t[layer][1][srow][kc * 64 + shalf * 32];
            float4* dh = (float4*)(smem + BH_OFF + srow * (SB * 2) + shalf * 64);
            float4* dl = (float4*)(smem + BL_OFF + srow * (SB * 2) + shalf * 64);
#pragma unroll
            for (int i = 0; i < 4; i++) { dh[i] = sh[i]; dl[i] = sl[i]; }
        }
        __syncthreads();
        mma_chunk(sbase + A1H_OFF, sbase + A1L_OFF, SA1,
                  sbase + BH_OFF, sbase + BL_OFF, C, r0, c0w, lane);
        __syncthreads();
    }

    // ================= Epilogue1: bias + relu + resplit into A2 =================
#pragma unroll
    for (int i = 0; i < 2; i++)
#pragma unroll
        for (int j = 0; j < 8; j++) {
            int col = c0w + j * 8 + (lane & 3) * 2;
            int row = r0 + i * 16 + (lane >> 2);
            float bb0 = b1[col], bb1 = b1[col + 1];
            uint32_t hi, lo;
            split2(fmaxf(C[i][j][0] + bb0, 0.0f), fmaxf(C[i][j][1] + bb1, 0.0f), hi, lo);
            *(uint32_t*)(smem + A2H_OFF + row * (SA2 * 2) + col * 2) = hi;
            *(uint32_t*)(smem + A2L_OFF + row * (SA2 * 2) + col * 2) = lo;
            split2(fmaxf(C[i][j][2] + bb0, 0.0f), fmaxf(C[i][j][3] + bb1, 0.0f), hi, lo);
            *(uint32_t*)(smem + A2H_OFF + (row + 8) * (SA2 * 2) + col * 2) = hi;
            *(uint32_t*)(smem + A2L_OFF + (row + 8) * (SA2 * 2) + col * 2) = lo;
        }
    __syncthreads();

    // ================= GEMM2: K=128 in 2 chunks =================
#pragma unroll
    for (int i = 0; i < 2; i++)
#pragma unroll
        for (int j = 0; j < 8; j++)
#pragma unroll
            for (int q = 0; q < 4; q++) C[i][j][q] = 0.0f;

    for (int kc = 0; kc < 2; kc++) {
        {
            const float4* sh = (const float4*)&g_ew2t[layer][0][srow][kc * 64 + shalf * 32];
            const float4* sl = (const float4*)&g_ew2t[layer][1][srow][kc * 64 + shalf * 32];
            float4* dh = (float4*)(smem + BH_OFF + srow * (SB * 2) + shalf * 64);
            float4* dl = (float4*)(smem + BL_OFF + srow * (SB * 2) + shalf * 64);
#pragma unroll
            for (int i = 0; i < 4; i++) { dh[i] = sh[i]; dl[i] = sl[i]; }
        }
        __syncthreads();
        mma_chunk(sbase + A2H_OFF + kc * 128, sbase + A2L_OFF + kc * 128, SA2,
                  sbase + BH_OFF, sbase + BL_OFF, C, r0, c0w, lane);
        __syncthreads();
    }

    // ================= Epilogue2: bias + scatter-add =================
#pragma unroll
    for (int i = 0; i < 2; i++) {
        int row = r0 + i * 16 + (lane >> 2);
        int d0 = g_dst[e0 + row];
        int d1 = g_dst[e0 + row + 8];
#pragma unroll
        for (int j = 0; j < 8; j++) {
            int col = c0w + j * 8 + (lane & 3) * 2;
            float bb0 = b2[col], bb1 = b2[col + 1];
            red_add_v2(&g_agg[(size_t)d0 * H + col], C[i][j][0] + bb0, C[i][j][1] + bb1);
            red_add_v2(&g_agg[(size_t)d1 * H + col], C[i][j][2] + bb0, C[i][j][3] + bb1);
        }
    }
}

// ---------------------------------------------------------------------------
// Node kernel (tensor-core mma.sync): 128 nodes/block; h += MLP([h,agg]);
// zeroes agg in place after reading.
// ---------------------------------------------------------------------------
__global__ __launch_bounds__(256, 2)
void node_kernel_mma(const float* __restrict__ b1,
                     const float* __restrict__ b2, int layer) {
    extern __shared__ char smem[];
    const uint32_t sbase = smem_u32(smem);
    const int tid = threadIdx.x;
    const int lane = tid & 31;
    const int wid = tid >> 5;
    const int n0 = blockIdx.x * ET;

    const int srow = tid >> 1;
    const int shalf = tid & 1;
    const int snode = n0 + srow;
    const int scn = snode < N_NODES ? snode : (N_NODES - 1);

    const int r0 = (wid >> 1) * 32;
    const int c0w = (wid & 1) * 64;

    float C[2][8][4];
#pragma unroll
    for (int i = 0; i < 2; i++)
#pragma unroll
        for (int j = 0; j < 8; j++)
#pragma unroll
            for (int q = 0; q < 4; q++) C[i][j][q] = 0.0f;

    // ================= GEMM1: K=256 ([h | agg]) in 4 chunks =================
    for (int kc = 0; kc < 4; kc++) {
        {
            const float* base = (kc < 2) ? g_h : g_agg;
            float4* hp = (float4*)&base[(size_t)scn * H + (kc & 1) * 64 + shalf * 32];
            uint32_t ph[16], pl[16];
#pragma unroll
            for (int i = 0; i < 8; i++) {
                float4 v = hp[i];
                split2(v.x, v.y, ph[2 * i],     pl[2 * i]);
                split2(v.z, v.w, ph[2 * i + 1], pl[2 * i + 1]);
            }
            // zero agg in place for next layer (unique reader per element)
            if (kc >= 2 && snode < N_NODES) {
                float4 z = make_float4(0.f, 0.f, 0.f, 0.f);
#pragma unroll
                for (int i = 0; i < 8; i++) hp[i] = z;
            }
            uint4* dh = (uint4*)(smem + A1H_OFF + srow * (SA1 * 2) + shalf * 64);
            uint4* dl = (uint4*)(smem + A1L_OFF + srow * (SA1 * 2) + shalf * 64);
#pragma unroll
            for (int i = 0; i < 4; i++) {
                dh[i] = make_uint4(ph[4 * i], ph[4 * i + 1], ph[4 * i + 2], ph[4 * i + 3]);
                dl[i] = make_uint4(pl[4 * i], pl[4 * i + 1], pl[4 * i + 2], pl[4 * i + 3]);
            }
        }
        {
            const float4* sh = (const float4*)&g_nw1t[layer][0][srow][kc * 64 + shalf * 32];
            const float4* sl = (const float4*)&g_nw1t[layer][1][srow][kc * 64 + shalf * 32];
            float4* dh = (float4*)(smem + BH_OFF + srow * (SB * 2) + shalf * 64);
            float4* dl = (float4*)(smem + BL_OFF + srow * (SB * 2) + shalf * 64);
#pragma unroll
            for (int i = 0; i < 4; i++) { dh[i] = sh[i]; dl[i] = sl[i]; }
        }
        __syncthreads();
        mma_chunk(sbase + A1H_OFF, sbase + A1L_OFF, SA1,
                  sbase + BH_OFF, sbase + BL_OFF, C, r0, c0w, lane);
        __syncthreads();
    }

    // ================= Epilogue1: bias + relu + resplit =================
#pragma unroll
    for (int i = 0; i < 2; i++)
#pragma unroll
        for (int j = 0; j < 8; j++) {
            int col = c0w + j * 8 + (lane & 3) * 2;
            int row = r0 + i * 16 + (lane >> 2);
            float bb0 = b1[col], bb1 = b1[col + 1];
            uint32_t hi, lo;
            split2(fmaxf(C[i][j][0] + bb0, 0.0f), fmaxf(C[i][j][1] + bb1, 0.0f), hi, lo);
            *(uint32_t*)(smem + A2H_OFF + row * (SA2 * 2) + col * 2) = hi;
            *(uint32_t*)(smem + A2L_OFF + row * (SA2 * 2) + col * 2) = lo;
            split2(fmaxf(C[i][j][2] + bb0, 0.0f), fmaxf(C[i][j][3] + bb1, 0.0f), hi, lo);
            *(uint32_t*)(smem + A2H_OFF + (row + 8) * (SA2 * 2) + col * 2) = hi;
            *(uint32_t*)(smem + A2L_OFF + (row + 8) * (SA2 * 2) + col * 2) = lo;
        }
    __syncthreads();

    // ================= GEMM2: K=128 in 2 chunks =================
#pragma unroll
    for (int i = 0; i < 2; i++)
#pragma unroll
        for (int j = 0; j < 8; j++)
#pragma unroll
            for (int q = 0; q < 4; q++) C[i][j][q] = 0.0f;

    for (int kc = 0; kc < 2; kc++) {
        {
            const float4* sh = (const float4*)&g_nw2t[layer][0][srow][kc * 64 + shalf * 32];
            const float4* sl = (const float4*)&g_nw2t[layer][1][srow][kc * 64 + shalf * 32];
            float4* dh = (float4*)(smem + BH_OFF + srow * (SB * 2) + shalf * 64);
            float4* dl = (float4*)(smem + BL_OFF + srow * (SB * 2) + shalf * 64);
#pragma unroll
            for (int i = 0; i < 4; i++) { dh[i] = sh[i]; dl[i] = sl[i]; }
        }
        __syncthreads();
        mma_chunk(sbase + A2H_OFF + kc * 128, sbase + A2L_OFF + kc * 128, SA2,
                  sbase + BH_OFF, sbase + BL_OFF, C, r0, c0w, lane);
        __syncthreads();
    }

    // ================= Epilogue2: residual h += C + b2 (block-owned rows) ====
#pragma unroll
    for (int i = 0; i < 2; i++) {
        int row = r0 + i * 16 + (lane >> 2);
        int nd0 = n0 + row;
        int nd1 = n0 + row + 8;
#pragma unroll
        for (int j = 0; j < 8; j++) {
            int col = c0w + j * 8 + (lane & 3) * 2;
            float bb0 = b2[col], bb1 = b2[col + 1];
            if (nd0 < N_NODES) {
                float2* p = (float2*)&g_h[(size_t)nd0 * H + col];
                float2 v = *p;
                v.x += C[i][j][0] + bb0;
                v.y += C[i][j][1] + bb1;
                *p = v;
            }
            if (nd1 < N_NODES) {
                float2* p = (float2*)&g_h[(size_t)nd1 * H + col];
                float2 v = *p;
                v.x += C[i][j][2] + bb0;
                v.y += C[i][j][3] + bb1;
                *p = v;
            }
        }
    }
}

// ---------------------------------------------------------------------------
// Decoder
// ---------------------------------------------------------------------------
__global__ void dec_kernel(const float* __restrict__ w,
                           const float* __restrict__ b,
                           float* __restrict__ out) {
    int idx = blockIdx.x * blockDim.x + threadIdx.x;
    if (idx >= N_NODES * NODE_OUT) return;
    int node = idx / NODE_OUT;
    int j = idx - node * NODE_OUT;
    float acc = b[j];
    const float* hp = &g_h[(size_t)node * H];
#pragma unroll 8
    for (int k = 0; k < H; k++)
        acc = fmaf(hp[k], w[k * NODE_OUT + j], acc);
    out[idx] = acc;
}

// ---------------------------------------------------------------------------
extern "C" void kernel_launch(void* const* d_in, const int* in_sizes, int n_in,
                              void* d_out, int out_size) {
    const float* x      = (const float*)d_in[0];
    const void*  ei     = d_in[1];
    const float* enc_w  = (const float*)d_in[2];
    const float* enc_b  = (const float*)d_in[3];
    const float* dec_w  = (const float*)d_in[4];
    const float* dec_b  = (const float*)d_in[5];
    const float* e_w1   = (const float*)d_in[6];
    const float* e_b1   = (const float*)d_in[7];
    const float* e_w2   = (const float*)d_in[8];
    const float* e_b2   = (const float*)d_in[9];
    const float* n_w1   = (const float*)d_in[10];
    const float* n_b1   = (const float*)d_in[11];
    const float* n_w2   = (const float*)d_in[12];
    const float* n_b2   = (const float*)d_in[13];
    float*       out    = (float*)d_out;

    static int attr_set = 0;
    if (!attr_set) {
        cudaFuncSetAttribute(edge_kernel_mma, cudaFuncAttributeMaxDynamicSharedMemorySize,
                             EDGE_SMEM);
        cudaFuncSetAttribute(node_kernel_mma, cudaFuncAttributeMaxDynamicSharedMemorySize,
                             EDGE_SMEM);
        attr_set = 1;
    }

    detect_kernel<<<1, 32>>>(ei);
    convert_kernel<<<(2 * N_EDGES + 255) / 256, 256>>>(ei);
    prep_w_kernel<<<(2 * N_LAYERS * (2 * H * H + H * H) + 255) / 256, 256>>>(
        e_w1, e_w2, n_w1, n_w2);
    enc_kernel<<<(N_NODES * H + 255) / 256, 256>>>(x, enc_w, enc_b);

    const int node_blocks = (N_NODES + ET - 1) / ET;
    for (int l = 0; l < N_LAYERS; l++) {
        edge_kernel_mma<<<N_EDGES / ET, 256, EDGE_SMEM>>>(
            e_b1 + (size_t)l * H, e_b2 + (size_t)l * H, l);
        node_kernel_mma<<<node_blocks, 256, EDGE_SMEM>>>(
            n_b1 + (size_t)l * H, n_b2 + (size_t)l * H, l);
    }

    dec_kernel<<<(N_NODES * NODE_OUT + 255) / 256, 256>>>(dec_w, dec_b, out);
}

// round 11
// speedup vs baseline: 3.4421x; 1.0860x over previous
#include <cuda_runtime.h>
#include <cuda_bf16.h>
#include <cstdint>

#define N_NODES 50000
#define N_EDGES 800000
#define NODE_IN 16
#define NODE_OUT 3
#define H 128
#define N_LAYERS 3

// ---- mma kernel params (shared by edge + node kernels)
#define ET 128                       // rows per block tile
// smem byte offsets (dynamic) — A2 overlays A1 (A1 dead after GEMM1)
#define A2H_OFF 0                    // [128][136] bf16 = 34816 B
#define A2L_OFF 34816
#define A1H_OFF 0                    // [128][72] bf16 = 18432 B (inside A2H)
#define A1L_OFF 34816                // (inside A2L)
#define BH_OFF  69632                // [128][72] bf16
#define BL_OFF  88064
#define EDGE_SMEM 106496             // fits 2 CTAs/SM
#define SA1 72                       // bf16 units per row (64 + 8 pad)
#define SB  72
#define SA2 136                      // 128 + 8 pad

typedef unsigned long long u64;

// ---------------------------------------------------------------------------
// Scratch (__device__ globals; alloc-free rule)
// ---------------------------------------------------------------------------
__device__ float g_h[N_NODES * H];
__device__ float g_agg[N_NODES * H];
__device__ __nv_bfloat16 g_hhi[N_NODES * H];   // persistent hi/lo split of h
__device__ __nv_bfloat16 g_hlo[N_NODES * H];
__device__ int   g_src[N_EDGES];
__device__ int   g_dst[N_EDGES];
__device__ int   g_is64;
// transposed hi/lo-split bf16 weights: w^T indexed [c][k]
__device__ __nv_bfloat16 g_ew1t[N_LAYERS][2][H][2 * H];
__device__ __nv_bfloat16 g_ew2t[N_LAYERS][2][H][H];
__device__ __nv_bfloat16 g_nw1t[N_LAYERS][2][H][2 * H];
__device__ __nv_bfloat16 g_nw2t[N_LAYERS][2][H][H];

// ---------------------------------------------------------------------------
// helpers
// ---------------------------------------------------------------------------
__device__ __forceinline__ uint32_t smem_u32(const void* p) {
    uint32_t a;
    asm("{ .reg .u64 t; cvta.to.shared.u64 t, %1; cvt.u32.u64 %0, t; }"
        : "=r"(a) : "l"(p));
    return a;
}
__device__ __forceinline__ void ldm_x4(uint32_t* r, uint32_t addr) {
    asm volatile("ldmatrix.sync.aligned.m8n8.x4.shared.b16 {%0,%1,%2,%3}, [%4];"
                 : "=r"(r[0]), "=r"(r[1]), "=r"(r[2]), "=r"(r[3]) : "r"(addr));
}
__device__ __forceinline__ void mma_bf16(float* c, const uint32_t* a, const uint32_t* b) {
    asm volatile(
        "mma.sync.aligned.m16n8k16.row.col.f32.bf16.bf16.f32 "
        "{%0,%1,%2,%3}, {%4,%5,%6,%7}, {%8,%9}, {%0,%1,%2,%3};"
        : "+f"(c[0]), "+f"(c[1]), "+f"(c[2]), "+f"(c[3])
        : "r"(a[0]), "r"(a[1]), "r"(a[2]), "r"(a[3]), "r"(b[0]), "r"(b[1]));
}
__device__ __forceinline__ void split2(float a, float b, uint32_t& hi, uint32_t& lo) {
    __nv_bfloat16 ha = __float2bfloat16(a), hb = __float2bfloat16(b);
    hi = (uint32_t)__bfloat16_as_ushort(ha) | ((uint32_t)__bfloat16_as_ushort(hb) << 16);
    __nv_bfloat16 la = __float2bfloat16(a - __bfloat162float(ha));
    __nv_bfloat16 lb = __float2bfloat16(b - __bfloat162float(hb));
    lo = (uint32_t)__bfloat16_as_ushort(la) | ((uint32_t)__bfloat16_as_ushort(lb) << 16);
}
__device__ __forceinline__ void red_add_v2(float* p, float a, float b) {
    asm volatile("red.global.add.v2.f32 [%0], {%1, %2};"
                 :: "l"(p), "f"(a), "f"(b) : "memory");
}

// ---------------------------------------------------------------------------
// dtype probe + convert
// ---------------------------------------------------------------------------
__global__ void detect_kernel(const void* __restrict__ ei) {
    if (threadIdx.x == 0 && blockIdx.x == 0) {
        const long long* p = (const long long*)ei;
        int is64 = 1;
        for (int i = 0; i < 256; i++) {
            long long v = p[i];
            if (v < 0 || v >= N_NODES) { is64 = 0; break; }
        }
        g_is64 = is64;
    }
}

__global__ void convert_kernel(const void* __restrict__ ei) {
    int i = blockIdx.x * blockDim.x + threadIdx.x;
    if (i >= 2 * N_EDGES) return;
    int v;
    if (g_is64) v = (int)((const long long*)ei)[i];
    else        v = ((const int*)ei)[i];
    if (i < N_EDGES) g_src[i] = v;
    else             g_dst[i - N_EDGES] = v;
}

// ---------------------------------------------------------------------------
// Weight prep: transposed hi/lo-split bf16 (w^T [c][k]) for edge + node MLPs
// ---------------------------------------------------------------------------
__global__ void prep_w_kernel(const float* __restrict__ e_w1,
                              const float* __restrict__ e_w2,
                              const float* __restrict__ n_w1,
                              const float* __restrict__ n_w2) {
    int idx = blockIdx.x * blockDim.x + threadIdx.x;
    const int W1E = N_LAYERS * 2 * H * H;
    const int W2E = N_LAYERS * H * H;
    if (idx < 2 * (W1E + W2E)) {
        int which = idx >= (W1E + W2E);               // 0 = edge, 1 = node
        int j = idx - which * (W1E + W2E);
        if (j < W1E) {
            int l = j / (2 * H * H);
            int rem = j % (2 * H * H);
            int k = rem / H, c = rem % H;
            float w = which ? n_w1[j] : e_w1[j];
            __nv_bfloat16 hi = __float2bfloat16(w);
            __nv_bfloat16 lo = __float2bfloat16(w - __bfloat162float(hi));
            if (which) { g_nw1t[l][0][c][k] = hi; g_nw1t[l][1][c][k] = lo; }
            else       { g_ew1t[l][0][c][k] = hi; g_ew1t[l][1][c][k] = lo; }
        } else {
            int q = j - W1E;
            int l = q / (H * H);
            int rem = q % (H * H);
            int k = rem / H, c = rem % H;
            float w = which ? n_w2[q] : e_w2[q];
            __nv_bfloat16 hi = __float2bfloat16(w);
            __nv_bfloat16 lo = __float2bfloat16(w - __bfloat162float(hi));
            if (which) { g_nw2t[l][0][c][k] = hi; g_nw2t[l][1][c][k] = lo; }
            else       { g_ew2t[l][0][c][k] = hi; g_ew2t[l][1][c][k] = lo; }
        }
    }
}

// ---------------------------------------------------------------------------
// Encoder (+ zero g_agg + write hi/lo split)
// ---------------------------------------------------------------------------
__global__ void enc_kernel(const float* __restrict__ x,
                           const float* __restrict__ w,
                           const float* __restrict__ b) {
    int idx = blockIdx.x * blockDim.x + threadIdx.x;
    if (idx >= N_NODES * H) return;
    int node = idx >> 7;
    int c = idx & (H - 1);
    float acc = b[c];
#pragma unroll
    for (int k = 0; k < NODE_IN; k++)
        acc = fmaf(x[node * NODE_IN + k], w[k * H + c], acc);
    g_h[idx] = acc;
    g_agg[idx] = 0.0f;
    __nv_bfloat16 hi = __float2bfloat16(acc);
    g_hhi[idx] = hi;
    g_hlo[idx] = __float2bfloat16(acc - __bfloat162float(hi));
}

// ---------------------------------------------------------------------------
// mma chunk: C += A(hi/lo)[rows r0..+31][k 0..63] x B^T cols c0w..+63 (3-pass)
// ---------------------------------------------------------------------------
__device__ __forceinline__ void mma_chunk(
    uint32_t a_hi, uint32_t a_lo, int astride,
    uint32_t b_hi, uint32_t b_lo,
    float C[2][8][4], int r0, int c0w, int lane)
{
    const int arow = lane & 15;
    const int acol = (lane >> 4) * 8;
    const int brow = (lane & 7) + ((lane >> 4) << 3);
    const int bcol = ((lane >> 3) & 1) * 8;
#pragma unroll
    for (int ks = 0; ks < 4; ks++) {
        uint32_t ah[2][4], al[2][4], bh[4][4], bl[4][4];
#pragma unroll
        for (int i = 0; i < 2; i++) {
            uint32_t off = (uint32_t)(((r0 + i * 16 + arow) * astride + ks * 16 + acol) * 2);
            ldm_x4(ah[i], a_hi + off);
            ldm_x4(al[i], a_lo + off);
        }
#pragma unroll
        for (int p = 0; p < 4; p++) {
            uint32_t off = (uint32_t)(((c0w + p * 16 + brow) * SB + ks * 16 + bcol) * 2);
            ldm_x4(bh[p], b_hi + off);
            ldm_x4(bl[p], b_lo + off);
        }
#pragma unroll
        for (int i = 0; i < 2; i++)
#pragma unroll
            for (int p = 0; p < 4; p++) {
                mma_bf16(C[i][2 * p],     ah[i], &bh[p][0]);
                mma_bf16(C[i][2 * p],     ah[i], &bl[p][0]);
                mma_bf16(C[i][2 * p],     al[i], &bh[p][0]);
                mma_bf16(C[i][2 * p + 1], ah[i], &bh[p][2]);
                mma_bf16(C[i][2 * p + 1], ah[i], &bl[p][2]);
                mma_bf16(C[i][2 * p + 1], al[i], &bh[p][2]);
            }
    }
}

// ---------------------------------------------------------------------------
// Edge kernel (tensor-core mma.sync): 128 edges/block, 8 warps, 2 CTAs/SM
// A staging = pure bf16 gather-copy (split precomputed per node).
// ---------------------------------------------------------------------------
__global__ __launch_bounds__(256, 2)
void edge_kernel_mma(const float* __restrict__ b1,
                     const float* __restrict__ b2, int layer) {
    extern __shared__ char smem[];
    const uint32_t sbase = smem_u32(smem);
    const int tid = threadIdx.x;
    const int lane = tid & 31;
    const int wid = tid >> 5;
    const int e0 = blockIdx.x * ET;

    const int srow = tid >> 1;
    const int shalf = tid & 1;
    const int ssrc = g_src[e0 + srow];
    const int sdst = g_dst[e0 + srow];

    const int r0 = (wid >> 1) * 32;
    const int c0w = (wid & 1) * 64;

    float C[2][8][4];
#pragma unroll
    for (int i = 0; i < 2; i++)
#pragma unroll
        for (int j = 0; j < 8; j++)
#pragma unroll
            for (int q = 0; q < 4; q++) C[i][j][q] = 0.0f;

    // ================= GEMM1: K=256 in 4 chunks of 64 =================
    for (int kc = 0; kc < 4; kc++) {
        {
            int node = (kc < 2) ? ssrc : sdst;
            size_t goff = (size_t)node * H + (kc & 1) * 64 + shalf * 32;
            const uint4* sh = (const uint4*)&g_hhi[goff];
            const uint4* sl = (const uint4*)&g_hlo[goff];
            uint4* dh = (uint4*)(smem + A1H_OFF + srow * (SA1 * 2) + shalf * 64);
            uint4* dl = (uint4*)(smem + A1L_OFF + srow * (SA1 * 2) + shalf * 64);
#pragma unroll
            for (int i = 0; i < 4; i++) { dh[i] = sh[i]; dl[i] = sl[i]; }
        }
        {
            const float4* sh = (const float4*)&g_ew1t[layer][0][srow][kc * 64 + shalf * 32];
            const float4* sl = (const float4*)&g_ew1t[layer][1][srow][kc * 64 + shalf * 32];
            float4* dh = (float4*)(smem + BH_OFF + srow * (SB * 2) + shalf * 64);
            float4* dl = (float4*)(smem + BL_OFF + srow * (SB * 2) + shalf * 64);
#pragma unroll
            for (int i = 0; i < 4; i++) { dh[i] = sh[i]; dl[i] = sl[i]; }
        }
        __syncthreads();
        mma_chunk(sbase + A1H_OFF, sbase + A1L_OFF, SA1,
                  sbase + BH_OFF, sbase + BL_OFF, C, r0, c0w, lane);
        __syncthreads();
    }

    // ================= Epilogue1: bias + relu + resplit into A2 =================
#pragma unroll
    for (int i = 0; i < 2; i++)
#pragma unroll
        for (int j = 0; j < 8; j++) {
            int col = c0w + j * 8 + (lane & 3) * 2;
            int row = r0 + i * 16 + (lane >> 2);
            float bb0 = b1[col], bb1 = b1[col + 1];
            uint32_t hi, lo;
            split2(fmaxf(C[i][j][0] + bb0, 0.0f), fmaxf(C[i][j][1] + bb1, 0.0f), hi, lo);
            *(uint32_t*)(smem + A2H_OFF + row * (SA2 * 2) + col * 2) = hi;
            *(uint32_t*)(smem + A2L_OFF + row * (SA2 * 2) + col * 2) = lo;
            split2(fmaxf(C[i][j][2] + bb0, 0.0f), fmaxf(C[i][j][3] + bb1, 0.0f), hi, lo);
            *(uint32_t*)(smem + A2H_OFF + (row + 8) * (SA2 * 2) + col * 2) = hi;
            *(uint32_t*)(smem + A2L_OFF + (row + 8) * (SA2 * 2) + col * 2) = lo;
        }
    __syncthreads();

    // ================= GEMM2: K=128 in 2 chunks =================
#pragma unroll
    for (int i = 0; i < 2; i++)
#pragma unroll
        for (int j = 0; j < 8; j++)
#pragma unroll
            for (int q = 0; q < 4; q++) C[i][j][q] = 0.0f;

    for (int kc = 0; kc < 2; kc++) {
        {
            const float4* sh = (const float4*)&g_ew2t[layer][0][srow][kc * 64 + shalf * 32];
            const float4* sl = (const float4*)&g_ew2t[layer][1][srow][kc * 64 + shalf * 32];
            float4* dh = (float4*)(smem + BH_OFF + srow * (SB * 2) + shalf * 64);
            float4* dl = (float4*)(smem + BL_OFF + srow * (SB * 2) + shalf * 64);
#pragma unroll
            for (int i = 0; i < 4; i++) { dh[i] = sh[i]; dl[i] = sl[i]; }
        }
        __syncthreads();
        mma_chunk(sbase + A2H_OFF + kc * 128, sbase + A2L_OFF + kc * 128, SA2,
                  sbase + BH_OFF, sbase + BL_OFF, C, r0, c0w, lane);
        __syncthreads();
    }

    // ================= Epilogue2: bias + scatter-add =================
#pragma unroll
    for (int i = 0; i < 2; i++) {
        int row = r0 + i * 16 + (lane >> 2);
        int d0 = g_dst[e0 + row];
        int d1 = g_dst[e0 + row + 8];
#pragma unroll
        for (int j = 0; j < 8; j++) {
            int col = c0w + j * 8 + (lane & 3) * 2;
            float bb0 = b2[col], bb1 = b2[col + 1];
            red_add_v2(&g_agg[(size_t)d0 * H + col], C[i][j][0] + bb0, C[i][j][1] + bb1);
            red_add_v2(&g_agg[(size_t)d1 * H + col], C[i][j][2] + bb0, C[i][j][3] + bb1);
        }
    }
}

// ---------------------------------------------------------------------------
// Node kernel (tensor-core mma.sync): 128 nodes/block; h += MLP([h,agg]);
// zeroes agg in place; writes fp32 h + bf16 hi/lo split for next layer.
// ---------------------------------------------------------------------------
__global__ __launch_bounds__(256, 2)
void node_kernel_mma(const float* __restrict__ b1,
                     const float* __restrict__ b2, int layer) {
    extern __shared__ char smem[];
    const uint32_t sbase = smem_u32(smem);
    const int tid = threadIdx.x;
    const int lane = tid & 31;
    const int wid = tid >> 5;
    const int n0 = blockIdx.x * ET;

    const int srow = tid >> 1;
    const int shalf = tid & 1;
    const int snode = n0 + srow;
    const int scn = snode < N_NODES ? snode : (N_NODES - 1);

    const int r0 = (wid >> 1) * 32;
    const int c0w = (wid & 1) * 64;

    float C[2][8][4];
#pragma unroll
    for (int i = 0; i < 2; i++)
#pragma unroll
        for (int j = 0; j < 8; j++)
#pragma unroll
            for (int q = 0; q < 4; q++) C[i][j][q] = 0.0f;

    // ================= GEMM1: K=256 ([h | agg]) in 4 chunks =================
    for (int kc = 0; kc < 4; kc++) {
        if (kc < 2) {
            // h chunks: precomputed split — pure copy
            size_t goff = (size_t)scn * H + kc * 64 + shalf * 32;
            const uint4* sh = (const uint4*)&g_hhi[goff];
            const uint4* sl = (const uint4*)&g_hlo[goff];
            uint4* dh = (uint4*)(smem + A1H_OFF + srow * (SA1 * 2) + shalf * 64);
            uint4* dl = (uint4*)(smem + A1L_OFF + srow * (SA1 * 2) + shalf * 64);
#pragma unroll
            for (int i = 0; i < 4; i++) { dh[i] = sh[i]; dl[i] = sl[i]; }
        } else {
            // agg chunks: split on the fly + zero in place
            float4* hp = (float4*)&g_agg[(size_t)scn * H + (kc & 1) * 64 + shalf * 32];
            uint32_t ph[16], pl[16];
#pragma unroll
            for (int i = 0; i < 8; i++) {
                float4 v = hp[i];
                split2(v.x, v.y, ph[2 * i],     pl[2 * i]);
                split2(v.z, v.w, ph[2 * i + 1], pl[2 * i + 1]);
            }
            if (snode < N_NODES) {
                float4 z = make_float4(0.f, 0.f, 0.f, 0.f);
#pragma unroll
                for (int i = 0; i < 8; i++) hp[i] = z;
            }
            uint4* dh = (uint4*)(smem + A1H_OFF + srow * (SA1 * 2) + shalf * 64);
            uint4* dl = (uint4*)(smem + A1L_OFF + srow * (SA1 * 2) + shalf * 64);
#pragma unroll
            for (int i = 0; i < 4; i++) {
                dh[i] = make_uint4(ph[4 * i], ph[4 * i + 1], ph[4 * i + 2], ph[4 * i + 3]);
                dl[i] = make_uint4(pl[4 * i], pl[4 * i + 1], pl[4 * i + 2], pl[4 * i + 3]);
            }
        }
        {
            const float4* sh = (const float4*)&g_nw1t[layer][0][srow][kc * 64 + shalf * 32];
            const float4* sl = (const float4*)&g_nw1t[layer][1][srow][kc * 64 + shalf * 32];
            float4* dh = (float4*)(smem + BH_OFF + srow * (SB * 2) + shalf * 64);
            float4* dl = (float4*)(smem + BL_OFF + srow * (SB * 2) + shalf * 64);
#pragma unroll
            for (int i = 0; i < 4; i++) { dh[i] = sh[i]; dl[i] = sl[i]; }
        }
        __syncthreads();
        mma_chunk(sbase + A1H_OFF, sbase + A1L_OFF, SA1,
                  sbase + BH_OFF, sbase + BL_OFF, C, r0, c0w, lane);
        __syncthreads();
    }

    // ================= Epilogue1: bias + relu + resplit =================
#pragma unroll
    for (int i = 0; i < 2; i++)
#pragma unroll
        for (int j = 0; j < 8; j++) {
            int col = c0w + j * 8 + (lane & 3) * 2;
            int row = r0 + i * 16 + (lane >> 2);
            float bb0 = b1[col], bb1 = b1[col + 1];
            uint32_t hi, lo;
            split2(fmaxf(C[i][j][0] + bb0, 0.0f), fmaxf(C[i][j][1] + bb1, 0.0f), hi, lo);
            *(uint32_t*)(smem + A2H_OFF + row * (SA2 * 2) + col * 2) = hi;
            *(uint32_t*)(smem + A2L_OFF + row * (SA2 * 2) + col * 2) = lo;
            split2(fmaxf(C[i][j][2] + bb0, 0.0f), fmaxf(C[i][j][3] + bb1, 0.0f), hi, lo);
            *(uint32_t*)(smem + A2H_OFF + (row + 8) * (SA2 * 2) + col * 2) = hi;
            *(uint32_t*)(smem + A2L_OFF + (row + 8) * (SA2 * 2) + col * 2) = lo;
        }
    __syncthreads();

    // ================= GEMM2: K=128 in 2 chunks =================
#pragma unroll
    for (int i = 0; i < 2; i++)
#pragma unroll
        for (int j = 0; j < 8; j++)
#pragma unroll
            for (int q = 0; q < 4; q++) C[i][j][q] = 0.0f;

    for (int kc = 0; kc < 2; kc++) {
        {
            const float4* sh = (const float4*)&g_nw2t[layer][0][srow][kc * 64 + shalf * 32];
            const float4* sl = (const float4*)&g_nw2t[layer][1][srow][kc * 64 + shalf * 32];
            float4* dh = (float4*)(smem + BH_OFF + srow * (SB * 2) + shalf * 64);
            float4* dl = (float4*)(smem + BL_OFF + srow * (SB * 2) + shalf * 64);
#pragma unroll
            for (int i = 0; i < 4; i++) { dh[i] = sh[i]; dl[i] = sl[i]; }
        }
        __syncthreads();
        mma_chunk(sbase + A2H_OFF + kc * 128, sbase + A2L_OFF + kc * 128, SA2,
                  sbase + BH_OFF, sbase + BL_OFF, C, r0, c0w, lane);
        __syncthreads();
    }

    // ======== Epilogue2: residual h += C + b2; write fp32 + bf16 split ========
#pragma unroll
    for (int i = 0; i < 2; i++) {
        int row = r0 + i * 16 + (lane >> 2);
        int nd0 = n0 + row;
        int nd1 = n0 + row + 8;
#pragma unroll
        for (int j = 0; j < 8; j++) {
            int col = c0w + j * 8 + (lane & 3) * 2;
            float bb0 = b2[col], bb1 = b2[col + 1];
            if (nd0 < N_NODES) {
                size_t off = (size_t)nd0 * H + col;
                float2* p = (float2*)&g_h[off];
                float2 v = *p;
                v.x += C[i][j][0] + bb0;
                v.y += C[i][j][1] + bb1;
                *p = v;
                uint32_t hi, lo;
                split2(v.x, v.y, hi, lo);
                *(uint32_t*)&g_hhi[off] = hi;
                *(uint32_t*)&g_hlo[off] = lo;
            }
            if (nd1 < N_NODES) {
                size_t off = (size_t)nd1 * H + col;
                float2* p = (float2*)&g_h[off];
                float2 v = *p;
                v.x += C[i][j][2] + bb0;
                v.y += C[i][j][3] + bb1;
                *p = v;
                uint32_t hi, lo;
                split2(v.x, v.y, hi, lo);
                *(uint32_t*)&g_hhi[off] = hi;
                *(uint32_t*)&g_hlo[off] = lo;
            }
        }
    }
}

// ---------------------------------------------------------------------------
// Decoder
// ---------------------------------------------------------------------------
__global__ void dec_kernel(const float* __restrict__ w,
                           const float* __restrict__ b,
                           float* __restrict__ out) {
    int idx = blockIdx.x * blockDim.x + threadIdx.x;
    if (idx >= N_NODES * NODE_OUT) return;
    int node = idx / NODE_OUT;
    int j = idx - node * NODE_OUT;
    float acc = b[j];
    const float* hp = &g_h[(size_t)node * H];
#pragma unroll 8
    for (int k = 0; k < H; k++)
        acc = fmaf(hp[k], w[k * NODE_OUT + j], acc);
    out[idx] = acc;
}

// ---------------------------------------------------------------------------
extern "C" void kernel_launch(void* const* d_in, const int* in_sizes, int n_in,
                              void* d_out, int out_size) {
    const float* x      = (const float*)d_in[0];
    const void*  ei     = d_in[1];
    const float* enc_w  = (const float*)d_in[2];
    const float* enc_b  = (const float*)d_in[3];
    const float* dec_w  = (const float*)d_in[4];
    const float* dec_b  = (const float*)d_in[5];
    const float* e_w1   = (const float*)d_in[6];
    const float* e_b1   = (const float*)d_in[7];
    const float* e_w2   = (const float*)d_in[8];
    const float* e_b2   = (const float*)d_in[9];
    const float* n_w1   = (const float*)d_in[10];
    const float* n_b1   = (const float*)d_in[11];
    const float* n_w2   = (const float*)d_in[12];
    const float* n_b2   = (const float*)d_in[13];
    float*       out    = (float*)d_out;

    static int attr_set = 0;
    if (!attr_set) {
        cudaFuncSetAttribute(edge_kernel_mma, cudaFuncAttributeMaxDynamicSharedMemorySize,
                             EDGE_SMEM);
        cudaFuncSetAttribute(node_kernel_mma, cudaFuncAttributeMaxDynamicSharedMemorySize,
                             EDGE_SMEM);
        attr_set = 1;
    }

    detect_kernel<<<1, 32>>>(ei);
    convert_kernel<<<(2 * N_EDGES + 255) / 256, 256>>>(ei);
    prep_w_kernel<<<(2 * N_LAYERS * (2 * H * H + H * H) + 255) / 256, 256>>>(
        e_w1, e_w2, n_w1, n_w2);
    enc_kernel<<<(N_NODES * H + 255) / 256, 256>>>(x, enc_w, enc_b);

    const int node_blocks = (N_NODES + ET - 1) / ET;
    for (int l = 0; l < N_LAYERS; l++) {
        edge_kernel_mma<<<N_EDGES / ET, 256, EDGE_SMEM>>>(
            e_b1 + (size_t)l * H, e_b2 + (size_t)l * H, l);
        node_kernel_mma<<<node_blocks, 256, EDGE_SMEM>>>(
            n_b1 + (size_t)l * H, n_b2 + (size_t)l * H, l);
    }

    dec_kernel<<<(N_NODES * NODE_OUT + 255) / 256, 256>>>(dec_w, dec_b, out);
}

// round 12
// speedup vs baseline: 3.4631x; 1.0061x over previous
#include <cuda_runtime.h>
#include <cuda_bf16.h>
#include <cstdint>

#define N_NODES 50000
#define N_EDGES 800000
#define NODE_IN 16
#define NODE_OUT 3
#define H 128
#define N_LAYERS 3

// ---- mma kernel params (shared by edge + node kernels)
#define ET 128                       // rows per block tile
// smem byte offsets (dynamic) — A2 overlays A1 (A1 dead after GEMM1)
#define A2H_OFF 0                    // [128][136] bf16 = 34816 B
#define A2L_OFF 34816
#define A1H_OFF 0                    // [128][72] bf16 = 18432 B (inside A2H)
#define A1L_OFF 34816                // (inside A2L)
#define BH_OFF  69632                // [128][72] bf16
#define BL_OFF  88064
#define EDGE_SMEM 106496             // fits 2 CTAs/SM
#define SA1 72                       // bf16 units per row (64 + 8 pad)
#define SB  72
#define SA2 136                      // 128 + 8 pad

typedef unsigned long long u64;

// ---------------------------------------------------------------------------
// Scratch (__device__ globals; alloc-free rule)
// ---------------------------------------------------------------------------
__device__ float g_h[N_NODES * H];
__device__ float g_agg[N_NODES * H];
__device__ __nv_bfloat16 g_hhi[N_NODES * H];   // persistent hi/lo split of h
__device__ __nv_bfloat16 g_hlo[N_NODES * H];
__device__ int   g_src[N_EDGES];
__device__ int   g_dst[N_EDGES];
__device__ int   g_is64;
// transposed hi/lo-split bf16 weights: w^T indexed [c][k]
__device__ __nv_bfloat16 g_ew1t[N_LAYERS][2][H][2 * H];
__device__ __nv_bfloat16 g_ew2t[N_LAYERS][2][H][H];
__device__ __nv_bfloat16 g_nw1t[N_LAYERS][2][H][2 * H];
__device__ __nv_bfloat16 g_nw2t[N_LAYERS][2][H][H];

// ---------------------------------------------------------------------------
// helpers
// ---------------------------------------------------------------------------
__device__ __forceinline__ uint32_t smem_u32(const void* p) {
    uint32_t a;
    asm("{ .reg .u64 t; cvta.to.shared.u64 t, %1; cvt.u32.u64 %0, t; }"
        : "=r"(a) : "l"(p));
    return a;
}
__device__ __forceinline__ void cp16(uint32_t saddr, const void* gptr) {
    asm volatile("cp.async.cg.shared.global [%0], [%1], 16;"
                 :: "r"(saddr), "l"(gptr) : "memory");
}
__device__ __forceinline__ void cp_commit_wait() {
    asm volatile("cp.async.commit_group;" ::: "memory");
    asm volatile("cp.async.wait_group 0;" ::: "memory");
}
__device__ __forceinline__ void ldm_x4(uint32_t* r, uint32_t addr) {
    asm volatile("ldmatrix.sync.aligned.m8n8.x4.shared.b16 {%0,%1,%2,%3}, [%4];"
                 : "=r"(r[0]), "=r"(r[1]), "=r"(r[2]), "=r"(r[3]) : "r"(addr));
}
__device__ __forceinline__ void mma_bf16(float* c, const uint32_t* a, const uint32_t* b) {
    asm volatile(
        "mma.sync.aligned.m16n8k16.row.col.f32.bf16.bf16.f32 "
        "{%0,%1,%2,%3}, {%4,%5,%6,%7}, {%8,%9}, {%0,%1,%2,%3};"
        : "+f"(c[0]), "+f"(c[1]), "+f"(c[2]), "+f"(c[3])
        : "r"(a[0]), "r"(a[1]), "r"(a[2]), "r"(a[3]), "r"(b[0]), "r"(b[1]));
}
__device__ __forceinline__ void split2(float a, float b, uint32_t& hi, uint32_t& lo) {
    __nv_bfloat16 ha = __float2bfloat16(a), hb = __float2bfloat16(b);
    hi = (uint32_t)__bfloat16_as_ushort(ha) | ((uint32_t)__bfloat16_as_ushort(hb) << 16);
    __nv_bfloat16 la = __float2bfloat16(a - __bfloat162float(ha));
    __nv_bfloat16 lb = __float2bfloat16(b - __bfloat162float(hb));
    lo = (uint32_t)__bfloat16_as_ushort(la) | ((uint32_t)__bfloat16_as_ushort(lb) << 16);
}
__device__ __forceinline__ void red_add_v2(float* p, float a, float b) {
    asm volatile("red.global.add.v2.f32 [%0], {%1, %2};"
                 :: "l"(p), "f"(a), "f"(b) : "memory");
}

// ---------------------------------------------------------------------------
// dtype probe + convert
// ---------------------------------------------------------------------------
__global__ void detect_kernel(const void* __restrict__ ei) {
    if (threadIdx.x == 0 && blockIdx.x == 0) {
        const long long* p = (const long long*)ei;
        int is64 = 1;
        for (int i = 0; i < 256; i++) {
            long long v = p[i];
            if (v < 0 || v >= N_NODES) { is64 = 0; break; }
        }
        g_is64 = is64;
    }
}

__global__ void convert_kernel(const void* __restrict__ ei) {
    int i = blockIdx.x * blockDim.x + threadIdx.x;
    if (i >= 2 * N_EDGES) return;
    int v;
    if (g_is64) v = (int)((const long long*)ei)[i];
    else        v = ((const int*)ei)[i];
    if (i < N_EDGES) g_src[i] = v;
    else             g_dst[i - N_EDGES] = v;
}

// ---------------------------------------------------------------------------
// Weight prep: transposed hi/lo-split bf16 (w^T [c][k]) for edge + node MLPs
// ---------------------------------------------------------------------------
__global__ void prep_w_kernel(const float* __restrict__ e_w1,
                              const float* __restrict__ e_w2,
                              const float* __restrict__ n_w1,
                              const float* __restrict__ n_w2) {
    int idx = blockIdx.x * blockDim.x + threadIdx.x;
    const int W1E = N_LAYERS * 2 * H * H;
    const int W2E = N_LAYERS * H * H;
    if (idx < 2 * (W1E + W2E)) {
        int which = idx >= (W1E + W2E);               // 0 = edge, 1 = node
        int j = idx - which * (W1E + W2E);
        if (j < W1E) {
            int l = j / (2 * H * H);
            int rem = j % (2 * H * H);
            int k = rem / H, c = rem % H;
            float w = which ? n_w1[j] : e_w1[j];
            __nv_bfloat16 hi = __float2bfloat16(w);
            __nv_bfloat16 lo = __float2bfloat16(w - __bfloat162float(hi));
            if (which) { g_nw1t[l][0][c][k] = hi; g_nw1t[l][1][c][k] = lo; }
            else       { g_ew1t[l][0][c][k] = hi; g_ew1t[l][1][c][k] = lo; }
        } else {
            int q = j - W1E;
            int l = q / (H * H);
            int rem = q % (H * H);
            int k = rem / H, c = rem % H;
            float w = which ? n_w2[q] : e_w2[q];
            __nv_bfloat16 hi = __float2bfloat16(w);
            __nv_bfloat16 lo = __float2bfloat16(w - __bfloat162float(hi));
            if (which) { g_nw2t[l][0][c][k] = hi; g_nw2t[l][1][c][k] = lo; }
            else       { g_ew2t[l][0][c][k] = hi; g_ew2t[l][1][c][k] = lo; }
        }
    }
}

// ---------------------------------------------------------------------------
// Encoder (+ zero g_agg + write hi/lo split)
// ---------------------------------------------------------------------------
__global__ void enc_kernel(const float* __restrict__ x,
                           const float* __restrict__ w,
                           const float* __restrict__ b) {
    int idx = blockIdx.x * blockDim.x + threadIdx.x;
    if (idx >= N_NODES * H) return;
    int node = idx >> 7;
    int c = idx & (H - 1);
    float acc = b[c];
#pragma unroll
    for (int k = 0; k < NODE_IN; k++)
        acc = fmaf(x[node * NODE_IN + k], w[k * H + c], acc);
    g_h[idx] = acc;
    g_agg[idx] = 0.0f;
    __nv_bfloat16 hi = __float2bfloat16(acc);
    g_hhi[idx] = hi;
    g_hlo[idx] = __float2bfloat16(acc - __bfloat162float(hi));
}

// ---------------------------------------------------------------------------
// mma chunk: C += A(hi/lo)[rows r0..+31][k 0..63] x B^T cols c0w..+63 (3-pass)
// ---------------------------------------------------------------------------
__device__ __forceinline__ void mma_chunk(
    uint32_t a_hi, uint32_t a_lo, int astride,
    uint32_t b_hi, uint32_t b_lo,
    float C[2][8][4], int r0, int c0w, int lane)
{
    const int arow = lane & 15;
    const int acol = (lane >> 4) * 8;
    const int brow = (lane & 7) + ((lane >> 4) << 3);
    const int bcol = ((lane >> 3) & 1) * 8;
#pragma unroll
    for (int ks = 0; ks < 4; ks++) {
        uint32_t ah[2][4], al[2][4], bh[4][4], bl[4][4];
#pragma unroll
        for (int i = 0; i < 2; i++) {
            uint32_t off = (uint32_t)(((r0 + i * 16 + arow) * astride + ks * 16 + acol) * 2);
            ldm_x4(ah[i], a_hi + off);
            ldm_x4(al[i], a_lo + off);
        }
#pragma unroll
        for (int p = 0; p < 4; p++) {
            uint32_t off = (uint32_t)(((c0w + p * 16 + brow) * SB + ks * 16 + bcol) * 2);
            ldm_x4(bh[p], b_hi + off);
            ldm_x4(bl[p], b_lo + off);
        }
#pragma unroll
        for (int i = 0; i < 2; i++)
#pragma unroll
            for (int p = 0; p < 4; p++) {
                mma_bf16(C[i][2 * p],     ah[i], &bh[p][0]);
                mma_bf16(C[i][2 * p],     ah[i], &bl[p][0]);
                mma_bf16(C[i][2 * p],     al[i], &bh[p][0]);
                mma_bf16(C[i][2 * p + 1], ah[i], &bh[p][2]);
                mma_bf16(C[i][2 * p + 1], ah[i], &bl[p][2]);
                mma_bf16(C[i][2 * p + 1], al[i], &bh[p][2]);
            }
    }
}

// ---------------------------------------------------------------------------
// Edge kernel (tensor-core mma.sync): 128 edges/block, 8 warps, 2 CTAs/SM
// cp.async staging throughout.
// ---------------------------------------------------------------------------
__global__ __launch_bounds__(256, 2)
void edge_kernel_mma(const float* __restrict__ b1,
                     const float* __restrict__ b2, int layer) {
    extern __shared__ char smem[];
    const uint32_t sbase = smem_u32(smem);
    const int tid = threadIdx.x;
    const int lane = tid & 31;
    const int wid = tid >> 5;
    const int e0 = blockIdx.x * ET;

    const int srow = tid >> 1;
    const int shalf = tid & 1;
    const int ssrc = g_src[e0 + srow];
    const int sdst = g_dst[e0 + srow];

    const int r0 = (wid >> 1) * 32;
    const int c0w = (wid & 1) * 64;

    // per-thread staging addresses
    const uint32_t a1h = sbase + A1H_OFF + srow * (SA1 * 2) + shalf * 64;
    const uint32_t a1l = sbase + A1L_OFF + srow * (SA1 * 2) + shalf * 64;
    const uint32_t bsh = sbase + BH_OFF + srow * (SB * 2) + shalf * 64;
    const uint32_t bsl = sbase + BL_OFF + srow * (SB * 2) + shalf * 64;

    float C[2][8][4];
#pragma unroll
    for (int i = 0; i < 2; i++)
#pragma unroll
        for (int j = 0; j < 8; j++)
#pragma unroll
            for (int q = 0; q < 4; q++) C[i][j][q] = 0.0f;

    // ================= GEMM1: K=256 in 4 chunks of 64 =================
    for (int kc = 0; kc < 4; kc++) {
        {
            int node = (kc < 2) ? ssrc : sdst;
            size_t goff = (size_t)node * H + (kc & 1) * 64 + shalf * 32;
            const __nv_bfloat16* sh = &g_hhi[goff];
            const __nv_bfloat16* sl = &g_hlo[goff];
#pragma unroll
            for (int i = 0; i < 4; i++) {
                cp16(a1h + i * 16, sh + i * 8);
                cp16(a1l + i * 16, sl + i * 8);
            }
        }
        {
            const __nv_bfloat16* sh = &g_ew1t[layer][0][srow][kc * 64 + shalf * 32];
            const __nv_bfloat16* sl = &g_ew1t[layer][1][srow][kc * 64 + shalf * 32];
#pragma unroll
            for (int i = 0; i < 4; i++) {
                cp16(bsh + i * 16, sh + i * 8);
                cp16(bsl + i * 16, sl + i * 8);
            }
        }
        cp_commit_wait();
        __syncthreads();
        mma_chunk(sbase + A1H_OFF, sbase + A1L_OFF, SA1,
                  sbase + BH_OFF, sbase + BL_OFF, C, r0, c0w, lane);
        __syncthreads();
    }

    // ===== Epilogue1 (bias+relu+resplit into A2) + stage GEMM2 B(kc=0) =====
    {
        const __nv_bfloat16* sh = &g_ew2t[layer][0][srow][shalf * 32];
        const __nv_bfloat16* sl = &g_ew2t[layer][1][srow][shalf * 32];
#pragma unroll
        for (int i = 0; i < 4; i++) {
            cp16(bsh + i * 16, sh + i * 8);
            cp16(bsl + i * 16, sl + i * 8);
        }
    }
#pragma unroll
    for (int i = 0; i < 2; i++)
#pragma unroll
        for (int j = 0; j < 8; j++) {
            int col = c0w + j * 8 + (lane & 3) * 2;
            int row = r0 + i * 16 + (lane >> 2);
            float bb0 = b1[col], bb1 = b1[col + 1];
            uint32_t hi, lo;
            split2(fmaxf(C[i][j][0] + bb0, 0.0f), fmaxf(C[i][j][1] + bb1, 0.0f), hi, lo);
            *(uint32_t*)(smem + A2H_OFF + row * (SA2 * 2) + col * 2) = hi;
            *(uint32_t*)(smem + A2L_OFF + row * (SA2 * 2) + col * 2) = lo;
            split2(fmaxf(C[i][j][2] + bb0, 0.0f), fmaxf(C[i][j][3] + bb1, 0.0f), hi, lo);
            *(uint32_t*)(smem + A2H_OFF + (row + 8) * (SA2 * 2) + col * 2) = hi;
            *(uint32_t*)(smem + A2L_OFF + (row + 8) * (SA2 * 2) + col * 2) = lo;
        }
    cp_commit_wait();
    __syncthreads();

    // ================= GEMM2: K=128 in 2 chunks =================
#pragma unroll
    for (int i = 0; i < 2; i++)
#pragma unroll
        for (int j = 0; j < 8; j++)
#pragma unroll
            for (int q = 0; q < 4; q++) C[i][j][q] = 0.0f;

    for (int kc = 0; kc < 2; kc++) {
        if (kc > 0) {
            const __nv_bfloat16* sh = &g_ew2t[layer][0][srow][kc * 64 + shalf * 32];
            const __nv_bfloat16* sl = &g_ew2t[layer][1][srow][kc * 64 + shalf * 32];
#pragma unroll
            for (int i = 0; i < 4; i++) {
                cp16(bsh + i * 16, sh + i * 8);
                cp16(bsl + i * 16, sl + i * 8);
            }
            cp_commit_wait();
            __syncthreads();
        }
        mma_chunk(sbase + A2H_OFF + kc * 128, sbase + A2L_OFF + kc * 128, SA2,
                  sbase + BH_OFF, sbase + BL_OFF, C, r0, c0w, lane);
        __syncthreads();
    }

    // ================= Epilogue2: bias + scatter-add =================
#pragma unroll
    for (int i = 0; i < 2; i++) {
        int row = r0 + i * 16 + (lane >> 2);
        int d0 = g_dst[e0 + row];
        int d1 = g_dst[e0 + row + 8];
#pragma unroll
        for (int j = 0; j < 8; j++) {
            int col = c0w + j * 8 + (lane & 3) * 2;
            float bb0 = b2[col], bb1 = b2[col + 1];
            red_add_v2(&g_agg[(size_t)d0 * H + col], C[i][j][0] + bb0, C[i][j][1] + bb1);
            red_add_v2(&g_agg[(size_t)d1 * H + col], C[i][j][2] + bb0, C[i][j][3] + bb1);
        }
    }
}

// ---------------------------------------------------------------------------
// Node kernel (tensor-core mma.sync): 128 nodes/block; h += MLP([h,agg]);
// zeroes agg in place; writes fp32 h + bf16 hi/lo split for next layer.
// ---------------------------------------------------------------------------
__global__ __launch_bounds__(256, 2)
void node_kernel_mma(const float* __restrict__ b1,
                     const float* __restrict__ b2, int layer) {
    extern __shared__ char smem[];
    const uint32_t sbase = smem_u32(smem);
    const int tid = threadIdx.x;
    const int lane = tid & 31;
    const int wid = tid >> 5;
    const int n0 = blockIdx.x * ET;

    const int srow = tid >> 1;
    const int shalf = tid & 1;
    const int snode = n0 + srow;
    const int scn = snode < N_NODES ? snode : (N_NODES - 1);

    const int r0 = (wid >> 1) * 32;
    const int c0w = (wid & 1) * 64;

    const uint32_t a1h = sbase + A1H_OFF + srow * (SA1 * 2) + shalf * 64;
    const uint32_t a1l = sbase + A1L_OFF + srow * (SA1 * 2) + shalf * 64;
    const uint32_t bsh = sbase + BH_OFF + srow * (SB * 2) + shalf * 64;
    const uint32_t bsl = sbase + BL_OFF + srow * (SB * 2) + shalf * 64;

    float C[2][8][4];
#pragma unroll
    for (int i = 0; i < 2; i++)
#pragma unroll
        for (int j = 0; j < 8; j++)
#pragma unroll
            for (int q = 0; q < 4; q++) C[i][j][q] = 0.0f;

    // ================= GEMM1: K=256 ([h | agg]) in 4 chunks =================
    for (int kc = 0; kc < 4; kc++) {
        if (kc < 2) {
            size_t goff = (size_t)scn * H + kc * 64 + shalf * 32;
            const __nv_bfloat16* sh = &g_hhi[goff];
            const __nv_bfloat16* sl = &g_hlo[goff];
#pragma unroll
            for (int i = 0; i < 4; i++) {
                cp16(a1h + i * 16, sh + i * 8);
                cp16(a1l + i * 16, sl + i * 8);
            }
        } else {
            // agg chunks: split on the fly + zero in place
            float4* hp = (float4*)&g_agg[(size_t)scn * H + (kc & 1) * 64 + shalf * 32];
            uint32_t ph[16], pl[16];
#pragma unroll
            for (int i = 0; i < 8; i++) {
                float4 v = hp[i];
                split2(v.x, v.y, ph[2 * i],     pl[2 * i]);
                split2(v.z, v.w, ph[2 * i + 1], pl[2 * i + 1]);
            }
            if (snode < N_NODES) {
                float4 z = make_float4(0.f, 0.f, 0.f, 0.f);
#pragma unroll
                for (int i = 0; i < 8; i++) hp[i] = z;
            }
            uint4* dh = (uint4*)(smem + A1H_OFF + srow * (SA1 * 2) + shalf * 64);
            uint4* dl = (uint4*)(smem + A1L_OFF + srow * (SA1 * 2) + shalf * 64);
#pragma unroll
            for (int i = 0; i < 4; i++) {
                dh[i] = make_uint4(ph[4 * i], ph[4 * i + 1], ph[4 * i + 2], ph[4 * i + 3]);
                dl[i] = make_uint4(pl[4 * i], pl[4 * i + 1], pl[4 * i + 2], pl[4 * i + 3]);
            }
        }
        {
            const __nv_bfloat16* sh = &g_nw1t[layer][0][srow][kc * 64 + shalf * 32];
            const __nv_bfloat16* sl = &g_nw1t[layer][1][srow][kc * 64 + shalf * 32];
#pragma unroll
            for (int i = 0; i < 4; i++) {
                cp16(bsh + i * 16, sh + i * 8);
                cp16(bsl + i * 16, sl + i * 8);
            }
        }
        cp_commit_wait();
        __syncthreads();
        mma_chunk(sbase + A1H_OFF, sbase + A1L_OFF, SA1,
                  sbase + BH_OFF, sbase + BL_OFF, C, r0, c0w, lane);
        __syncthreads();
    }

    // ===== Epilogue1 + stage GEMM2 B(kc=0) =====
    {
        const __nv_bfloat16* sh = &g_nw2t[layer][0][srow][shalf * 32];
        const __nv_bfloat16* sl = &g_nw2t[layer][1][srow][shalf * 32];
#pragma unroll
        for (int i = 0; i < 4; i++) {
            cp16(bsh + i * 16, sh + i * 8);
            cp16(bsl + i * 16, sl + i * 8);
        }
    }
#pragma unroll
    for (int i = 0; i < 2; i++)
#pragma unroll
        for (int j = 0; j < 8; j++) {
            int col = c0w + j * 8 + (lane & 3) * 2;
            int row = r0 + i * 16 + (lane >> 2);
            float bb0 = b1[col], bb1 = b1[col + 1];
            uint32_t hi, lo;
            split2(fmaxf(C[i][j][0] + bb0, 0.0f), fmaxf(C[i][j][1] + bb1, 0.0f), hi, lo);
            *(uint32_t*)(smem + A2H_OFF + row * (SA2 * 2) + col * 2) = hi;
            *(uint32_t*)(smem + A2L_OFF + row * (SA2 * 2) + col * 2) = lo;
            split2(fmaxf(C[i][j][2] + bb0, 0.0f), fmaxf(C[i][j][3] + bb1, 0.0f), hi, lo);
            *(uint32_t*)(smem + A2H_OFF + (row + 8) * (SA2 * 2) + col * 2) = hi;
            *(uint32_t*)(smem + A2L_OFF + (row + 8) * (SA2 * 2) + col * 2) = lo;
        }
    cp_commit_wait();
    __syncthreads();

    // ================= GEMM2: K=128 in 2 chunks =================
#pragma unroll
    for (int i = 0; i < 2; i++)
#pragma unroll
        for (int j = 0; j < 8; j++)
#pragma unroll
            for (int q = 0; q < 4; q++) C[i][j][q] = 0.0f;

    for (int kc = 0; kc < 2; kc++) {
        if (kc > 0) {
            const __nv_bfloat16* sh = &g_nw2t[layer][0][srow][kc * 64 + shalf * 32];
            const __nv_bfloat16* sl = &g_nw2t[layer][1][srow][kc * 64 + shalf * 32];
#pragma unroll
            for (int i = 0; i < 4; i++) {
                cp16(bsh + i * 16, sh + i * 8);
                cp16(bsl + i * 16, sl + i * 8);
            }
            cp_commit_wait();
            __syncthreads();
        }
        mma_chunk(sbase + A2H_OFF + kc * 128, sbase + A2L_OFF + kc * 128, SA2,
                  sbase + BH_OFF, sbase + BL_OFF, C, r0, c0w, lane);
        __syncthreads();
    }

    // ======== Epilogue2: residual h += C + b2; write fp32 + bf16 split ========
#pragma unroll
    for (int i = 0; i < 2; i++) {
        int row = r0 + i * 16 + (lane >> 2);
        int nd0 = n0 + row;
        int nd1 = n0 + row + 8;
#pragma unroll
        for (int j = 0; j < 8; j++) {
            int col = c0w + j * 8 + (lane & 3) * 2;
            float bb0 = b2[col], bb1 = b2[col + 1];
            if (nd0 < N_NODES) {
                size_t off = (size_t)nd0 * H + col;
                float2* p = (float2*)&g_h[off];
                float2 v = *p;
                v.x += C[i][j][0] + bb0;
                v.y += C[i][j][1] + bb1;
                *p = v;
                uint32_t hi, lo;
                split2(v.x, v.y, hi, lo);
                *(uint32_t*)&g_hhi[off] = hi;
                *(uint32_t*)&g_hlo[off] = lo;
            }
            if (nd1 < N_NODES) {
                size_t off = (size_t)nd1 * H + col;
                float2* p = (float2*)&g_h[off];
                float2 v = *p;
                v.x += C[i][j][2] + bb0;
                v.y += C[i][j][3] + bb1;
                *p = v;
                uint32_t hi, lo;
                split2(v.x, v.y, hi, lo);
                *(uint32_t*)&g_hhi[off] = hi;
                *(uint32_t*)&g_hlo[off] = lo;
            }
        }
    }
}

// ---------------------------------------------------------------------------
// Decoder
// ---------------------------------------------------------------------------
__global__ void dec_kernel(const float* __restrict__ w,
                           const float* __restrict__ b,
                           float* __restrict__ out) {
    int idx = blockIdx.x * blockDim.x + threadIdx.x;
    if (idx >= N_NODES * NODE_OUT) return;
    int node = idx / NODE_OUT;
    int j = idx - node * NODE_OUT;
    float acc = b[j];
    const float* hp = &g_h[(size_t)node * H];
#pragma unroll 8
    for (int k = 0; k < H; k++)
        acc = fmaf(hp[k], w[k * NODE_OUT + j], acc);
    out[idx] = acc;
}

// ---------------------------------------------------------------------------
extern "C" void kernel_launch(void* const* d_in, const int* in_sizes, int n_in,
                              void* d_out, int out_size) {
    const float* x      = (const float*)d_in[0];
    const void*  ei     = d_in[1];
    const float* enc_w  = (const float*)d_in[2];
    const float* enc_b  = (const float*)d_in[3];
    const float* dec_w  = (const float*)d_in[4];
    const float* dec_b  = (const float*)d_in[5];
    const float* e_w1   = (const float*)d_in[6];
    const float* e_b1   = (const float*)d_in[7];
    const float* e_w2   = (const float*)d_in[8];
    const float* e_b2   = (const float*)d_in[9];
    const float* n_w1   = (const float*)d_in[10];
    const float* n_b1   = (const float*)d_in[11];
    const float* n_w2   = (const float*)d_in[12];
    const float* n_b2   = (const float*)d_in[13];
    float*       out    = (float*)d_out;

    static int attr_set = 0;
    if (!attr_set) {
        cudaFuncSetAttribute(edge_kernel_mma, cudaFuncAttributeMaxDynamicSharedMemorySize,
                             EDGE_SMEM);
        cudaFuncSetAttribute(node_kernel_mma, cudaFuncAttributeMaxDynamicSharedMemorySize,
                             EDGE_SMEM);
        attr_set = 1;
    }

    detect_kernel<<<1, 32>>>(ei);
    convert_kernel<<<(2 * N_EDGES + 255) / 256, 256>>>(ei);
    prep_w_kernel<<<(2 * N_LAYERS * (2 * H * H + H * H) + 255) / 256, 256>>>(
        e_w1, e_w2, n_w1, n_w2);
    enc_kernel<<<(N_NODES * H + 255) / 256, 256>>>(x, enc_w, enc_b);

    const int node_blocks = (N_NODES + ET - 1) / ET;
    for (int l = 0; l < N_LAYERS; l++) {
        edge_kernel_mma<<<N_EDGES / ET, 256, EDGE_SMEM>>>(
            e_b1 + (size_t)l * H, e_b2 + (size_t)l * H, l);
        node_kernel_mma<<<node_blocks, 256, EDGE_SMEM>>>(
            n_b1 + (size_t)l * H, n_b2 + (size_t)l * H, l);
    }

    dec_kernel<<<(N_NODES * NODE_OUT + 255) / 256, 256>>>(dec_w, dec_b, out);
}

// round 13
// speedup vs baseline: 4.2752x; 1.2345x over previous
#include <cuda_runtime.h>
#include <cuda_bf16.h>
#include <cstdint>

#define N_NODES 50000
#define N_EDGES 800000
#define NODE_IN 16
#define NODE_OUT 3
#define H 128
#define N_LAYERS 3

// ---- mma tile params
#define ET 128                       // rows per block tile
// edge/node kernel smem — A2 overlays A1
#define A2H_OFF 0                    // [128][136] bf16 = 34816 B
#define A2L_OFF 34816
#define A1H_OFF 0                    // [128][72] bf16 (inside A2H)
#define A1L_OFF 34816
#define BH_OFF  69632                // [128][72] bf16
#define BL_OFF  88064
#define EDGE_SMEM 106496             // 2 CTAs/SM
// prep_p kernel smem
#define PA_H 0
#define PA_L 18432
#define PB_H 36864
#define PB_L 55296
#define PREP_SMEM 73728
#define SA1 72
#define SB  72
#define SA2 136

typedef unsigned long long u64;

// ---------------------------------------------------------------------------
// Scratch (__device__ globals; alloc-free rule)
// ---------------------------------------------------------------------------
__device__ float g_h[N_NODES * H];
__device__ float g_agg[N_NODES * H];
__device__ float g_p1[N_NODES * H];            // h@W1_top + b1 (per layer)
__device__ float g_p2[N_NODES * H];            // h@W1_bot
__device__ __nv_bfloat16 g_hhi[N_NODES * H];   // persistent hi/lo split of h
__device__ __nv_bfloat16 g_hlo[N_NODES * H];
__device__ int   g_src[N_EDGES];
__device__ int   g_dst[N_EDGES];
__device__ int   g_is64;
// transposed hi/lo-split bf16 weights: w^T indexed [c][k]
__device__ __nv_bfloat16 g_ew1t[N_LAYERS][2][H][2 * H];
__device__ __nv_bfloat16 g_ew2t[N_LAYERS][2][H][H];
__device__ __nv_bfloat16 g_nw1t[N_LAYERS][2][H][2 * H];
__device__ __nv_bfloat16 g_nw2t[N_LAYERS][2][H][H];

// ---------------------------------------------------------------------------
// helpers
// ---------------------------------------------------------------------------
__device__ __forceinline__ uint32_t smem_u32(const void* p) {
    uint32_t a;
    asm("{ .reg .u64 t; cvta.to.shared.u64 t, %1; cvt.u32.u64 %0, t; }"
        : "=r"(a) : "l"(p));
    return a;
}
__device__ __forceinline__ void cp16(uint32_t saddr, const void* gptr) {
    asm volatile("cp.async.cg.shared.global [%0], [%1], 16;"
                 :: "r"(saddr), "l"(gptr) : "memory");
}
__device__ __forceinline__ void cp_commit_wait() {
    asm volatile("cp.async.commit_group;" ::: "memory");
    asm volatile("cp.async.wait_group 0;" ::: "memory");
}
__device__ __forceinline__ void ldm_x4(uint32_t* r, uint32_t addr) {
    asm volatile("ldmatrix.sync.aligned.m8n8.x4.shared.b16 {%0,%1,%2,%3}, [%4];"
                 : "=r"(r[0]), "=r"(r[1]), "=r"(r[2]), "=r"(r[3]) : "r"(addr));
}
__device__ __forceinline__ void mma_bf16(float* c, const uint32_t* a, const uint32_t* b) {
    asm volatile(
        "mma.sync.aligned.m16n8k16.row.col.f32.bf16.bf16.f32 "
        "{%0,%1,%2,%3}, {%4,%5,%6,%7}, {%8,%9}, {%0,%1,%2,%3};"
        : "+f"(c[0]), "+f"(c[1]), "+f"(c[2]), "+f"(c[3])
        : "r"(a[0]), "r"(a[1]), "r"(a[2]), "r"(a[3]), "r"(b[0]), "r"(b[1]));
}
__device__ __forceinline__ void split2(float a, float b, uint32_t& hi, uint32_t& lo) {
    __nv_bfloat16 ha = __float2bfloat16(a), hb = __float2bfloat16(b);
    hi = (uint32_t)__bfloat16_as_ushort(ha) | ((uint32_t)__bfloat16_as_ushort(hb) << 16);
    __nv_bfloat16 la = __float2bfloat16(a - __bfloat162float(ha));
    __nv_bfloat16 lb = __float2bfloat16(b - __bfloat162float(hb));
    lo = (uint32_t)__bfloat16_as_ushort(la) | ((uint32_t)__bfloat16_as_ushort(lb) << 16);
}
__device__ __forceinline__ void red_add_v2(float* p, float a, float b) {
    asm volatile("red.global.add.v2.f32 [%0], {%1, %2};"
                 :: "l"(p), "f"(a), "f"(b) : "memory");
}

// ---------------------------------------------------------------------------
// dtype probe + convert
// ---------------------------------------------------------------------------
__global__ void detect_kernel(const void* __restrict__ ei) {
    if (threadIdx.x == 0 && blockIdx.x == 0) {
        const long long* p = (const long long*)ei;
        int is64 = 1;
        for (int i = 0; i < 256; i++) {
            long long v = p[i];
            if (v < 0 || v >= N_NODES) { is64 = 0; break; }
        }
        g_is64 = is64;
    }
}

__global__ void convert_kernel(const void* __restrict__ ei) {
    int i = blockIdx.x * blockDim.x + threadIdx.x;
    if (i >= 2 * N_EDGES) return;
    int v;
    if (g_is64) v = (int)((const long long*)ei)[i];
    else        v = ((const int*)ei)[i];
    if (i < N_EDGES) g_src[i] = v;
    else             g_dst[i - N_EDGES] = v;
}

// ---------------------------------------------------------------------------
// Weight prep: transposed hi/lo-split bf16 (w^T [c][k]) for edge + node MLPs
// ---------------------------------------------------------------------------
__global__ void prep_w_kernel(const float* __restrict__ e_w1,
                              const float* __restrict__ e_w2,
                              const float* __restrict__ n_w1,
                              const float* __restrict__ n_w2) {
    int idx = blockIdx.x * blockDim.x + threadIdx.x;
    const int W1E = N_LAYERS * 2 * H * H;
    const int W2E = N_LAYERS * H * H;
    if (idx < 2 * (W1E + W2E)) {
        int which = idx >= (W1E + W2E);               // 0 = edge, 1 = node
        int j = idx - which * (W1E + W2E);
        if (j < W1E) {
            int l = j / (2 * H * H);
            int rem = j % (2 * H * H);
            int k = rem / H, c = rem % H;
            float w = which ? n_w1[j] : e_w1[j];
            __nv_bfloat16 hi = __float2bfloat16(w);
            __nv_bfloat16 lo = __float2bfloat16(w - __bfloat162float(hi));
            if (which) { g_nw1t[l][0][c][k] = hi; g_nw1t[l][1][c][k] = lo; }
            else       { g_ew1t[l][0][c][k] = hi; g_ew1t[l][1][c][k] = lo; }
        } else {
            int q = j - W1E;
            int l = q / (H * H);
            int rem = q % (H * H);
            int k = rem / H, c = rem % H;
            float w = which ? n_w2[q] : e_w2[q];
            __nv_bfloat16 hi = __float2bfloat16(w);
            __nv_bfloat16 lo = __float2bfloat16(w - __bfloat162float(hi));
            if (which) { g_nw2t[l][0][c][k] = hi; g_nw2t[l][1][c][k] = lo; }
            else       { g_ew2t[l][0][c][k] = hi; g_ew2t[l][1][c][k] = lo; }
        }
    }
}

// ---------------------------------------------------------------------------
// Encoder (+ zero g_agg + write hi/lo split)
// ---------------------------------------------------------------------------
__global__ void enc_kernel(const float* __restrict__ x,
                           const float* __restrict__ w,
                           const float* __restrict__ b) {
    int idx = blockIdx.x * blockDim.x + threadIdx.x;
    if (idx >= N_NODES * H) return;
    int node = idx >> 7;
    int c = idx & (H - 1);
    float acc = b[c];
#pragma unroll
    for (int k = 0; k < NODE_IN; k++)
        acc = fmaf(x[node * NODE_IN + k], w[k * H + c], acc);
    g_h[idx] = acc;
    g_agg[idx] = 0.0f;
    __nv_bfloat16 hi = __float2bfloat16(acc);
    g_hhi[idx] = hi;
    g_hlo[idx] = __float2bfloat16(acc - __bfloat162float(hi));
}

// ---------------------------------------------------------------------------
// mma chunk: C += A(hi/lo)[rows r0..+31][k 0..63] x B^T cols c0w..+63 (3-pass)
// ---------------------------------------------------------------------------
__device__ __forceinline__ void mma_chunk(
    uint32_t a_hi, uint32_t a_lo, int astride,
    uint32_t b_hi, uint32_t b_lo,
    float C[2][8][4], int r0, int c0w, int lane)
{
    const int arow = lane & 15;
    const int acol = (lane >> 4) * 8;
    const int brow = (lane & 7) + ((lane >> 4) << 3);
    const int bcol = ((lane >> 3) & 1) * 8;
#pragma unroll
    for (int ks = 0; ks < 4; ks++) {
        uint32_t ah[2][4], al[2][4], bh[4][4], bl[4][4];
#pragma unroll
        for (int i = 0; i < 2; i++) {
            uint32_t off = (uint32_t)(((r0 + i * 16 + arow) * astride + ks * 16 + acol) * 2);
            ldm_x4(ah[i], a_hi + off);
            ldm_x4(al[i], a_lo + off);
        }
#pragma unroll
        for (int p = 0; p < 4; p++) {
            uint32_t off = (uint32_t)(((c0w + p * 16 + brow) * SB + ks * 16 + bcol) * 2);
            ldm_x4(bh[p], b_hi + off);
            ldm_x4(bl[p], b_lo + off);
        }
#pragma unroll
        for (int i = 0; i < 2; i++)
#pragma unroll
            for (int p = 0; p < 4; p++) {
                mma_bf16(C[i][2 * p],     ah[i], &bh[p][0]);
                mma_bf16(C[i][2 * p],     ah[i], &bl[p][0]);
                mma_bf16(C[i][2 * p],     al[i], &bh[p][0]);
                mma_bf16(C[i][2 * p + 1], ah[i], &bh[p][2]);
                mma_bf16(C[i][2 * p + 1], ah[i], &bl[p][2]);
                mma_bf16(C[i][2 * p + 1], al[i], &bh[p][2]);
            }
    }
}

// ---------------------------------------------------------------------------
// prep_p kernel: P1 = h@W1_top + b1, P2 = h@W1_bot   (per 128-node tile)
// ---------------------------------------------------------------------------
__global__ __launch_bounds__(256, 2)
void prep_p_kernel(const float* __restrict__ b1, int layer) {
    extern __shared__ char smem[];
    const uint32_t sbase = smem_u32(smem);
    const int tid = threadIdx.x;
    const int lane = tid & 31;
    const int wid = tid >> 5;
    const int n0 = blockIdx.x * ET;

    const int srow = tid >> 1;
    const int shalf = tid & 1;
    const int snode = n0 + srow;
    const int scn = snode < N_NODES ? snode : (N_NODES - 1);

    const int r0 = (wid >> 1) * 32;
    const int c0w = (wid & 1) * 64;

    const uint32_t pah = sbase + PA_H + srow * (SA1 * 2) + shalf * 64;
    const uint32_t pal = sbase + PA_L + srow * (SA1 * 2) + shalf * 64;
    const uint32_t pbh = sbase + PB_H + srow * (SB * 2) + shalf * 64;
    const uint32_t pbl = sbase + PB_L + srow * (SB * 2) + shalf * 64;

    for (int out = 0; out < 2; out++) {
        float C[2][8][4];
#pragma unroll
        for (int i = 0; i < 2; i++)
#pragma unroll
            for (int j = 0; j < 8; j++)
#pragma unroll
                for (int q = 0; q < 4; q++) C[i][j][q] = 0.0f;

        for (int kc = 0; kc < 2; kc++) {
            {
                size_t goff = (size_t)scn * H + kc * 64 + shalf * 32;
                const __nv_bfloat16* sh = &g_hhi[goff];
                const __nv_bfloat16* sl = &g_hlo[goff];
#pragma unroll
                for (int i = 0; i < 4; i++) {
                    cp16(pah + i * 16, sh + i * 8);
                    cp16(pal + i * 16, sl + i * 8);
                }
            }
            {
                int koff = out * 128 + kc * 64 + shalf * 32;
                const __nv_bfloat16* sh = &g_ew1t[layer][0][srow][koff];
                const __nv_bfloat16* sl = &g_ew1t[layer][1][srow][koff];
#pragma unroll
                for (int i = 0; i < 4; i++) {
                    cp16(pbh + i * 16, sh + i * 8);
                    cp16(pbl + i * 16, sl + i * 8);
                }
            }
            cp_commit_wait();
            __syncthreads();
            mma_chunk(sbase + PA_H, sbase + PA_L, SA1,
                      sbase + PB_H, sbase + PB_L, C, r0, c0w, lane);
            __syncthreads();
        }

        float* dst = out ? g_p2 : g_p1;
#pragma unroll
        for (int i = 0; i < 2; i++) {
            int row = r0 + i * 16 + (lane >> 2);
            int nd0 = n0 + row;
            int nd1 = n0 + row + 8;
#pragma unroll
            for (int j = 0; j < 8; j++) {
                int col = c0w + j * 8 + (lane & 3) * 2;
                float bb0 = out ? 0.0f : b1[col];
                float bb1 = out ? 0.0f : b1[col + 1];
                if (nd0 < N_NODES)
                    *(float2*)&dst[(size_t)nd0 * H + col] =
                        make_float2(C[i][j][0] + bb0, C[i][j][1] + bb1);
                if (nd1 < N_NODES)
                    *(float2*)&dst[(size_t)nd1 * H + col] =
                        make_float2(C[i][j][2] + bb0, C[i][j][3] + bb1);
            }
        }
    }
}

// ---------------------------------------------------------------------------
// Edge kernel: e = relu(P1[src] + P2[dst]) @ W2 + b2 ; scatter into g_agg.
// GEMM1 eliminated via P factorization. 128 edges/block, 2 CTAs/SM.
// ---------------------------------------------------------------------------
__global__ __launch_bounds__(256, 2)
void edge_kernel_mma(const float* __restrict__ b2, int layer) {
    extern __shared__ char smem[];
    const uint32_t sbase = smem_u32(smem);
    const int tid = threadIdx.x;
    const int lane = tid & 31;
    const int wid = tid >> 5;
    const int e0 = blockIdx.x * ET;

    const int srow = tid >> 1;
    const int shalf = tid & 1;
    const int ssrc = g_src[e0 + srow];
    const int sdst = g_dst[e0 + srow];

    const int r0 = (wid >> 1) * 32;
    const int c0w = (wid & 1) * 64;

    const uint32_t bsh = sbase + BH_OFF + srow * (SB * 2) + shalf * 64;
    const uint32_t bsl = sbase + BL_OFF + srow * (SB * 2) + shalf * 64;

    // stage B chunk 0 (in flight while we build A2)
    {
        const __nv_bfloat16* sh = &g_ew2t[layer][0][srow][shalf * 32];
        const __nv_bfloat16* sl = &g_ew2t[layer][1][srow][shalf * 32];
#pragma unroll
        for (int i = 0; i < 4; i++) {
            cp16(bsh + i * 16, sh + i * 8);
            cp16(bsl + i * 16, sl + i * 8);
        }
    }

    // build A2 = split(relu(P1[src] + P2[dst])): 2 threads/row, 64 cols each
    {
        const float4* p1 = (const float4*)&g_p1[(size_t)ssrc * H + shalf * 64];
        const float4* p2 = (const float4*)&g_p2[(size_t)sdst * H + shalf * 64];
        char* ah = smem + A2H_OFF + srow * (SA2 * 2) + shalf * 128;
        char* al = smem + A2L_OFF + srow * (SA2 * 2) + shalf * 128;
#pragma unroll
        for (int i = 0; i < 16; i++) {
            float4 a = p1[i];
            float4 b = p2[i];
            float v0 = fmaxf(a.x + b.x, 0.0f);
            float v1 = fmaxf(a.y + b.y, 0.0f);
            float v2 = fmaxf(a.z + b.z, 0.0f);
            float v3 = fmaxf(a.w + b.w, 0.0f);
            uint32_t h01, l01, h23, l23;
            split2(v0, v1, h01, l01);
            split2(v2, v3, h23, l23);
            *(uint2*)(ah + i * 8) = make_uint2(h01, h23);
            *(uint2*)(al + i * 8) = make_uint2(l01, l23);
        }
    }
    cp_commit_wait();
    __syncthreads();

    // ================= GEMM2: K=128 in 2 chunks =================
    float C[2][8][4];
#pragma unroll
    for (int i = 0; i < 2; i++)
#pragma unroll
        for (int j = 0; j < 8; j++)
#pragma unroll
            for (int q = 0; q < 4; q++) C[i][j][q] = 0.0f;

    for (int kc = 0; kc < 2; kc++) {
        if (kc > 0) {
            const __nv_bfloat16* sh = &g_ew2t[layer][0][srow][kc * 64 + shalf * 32];
            const __nv_bfloat16* sl = &g_ew2t[layer][1][srow][kc * 64 + shalf * 32];
#pragma unroll
            for (int i = 0; i < 4; i++) {
                cp16(bsh + i * 16, sh + i * 8);
                cp16(bsl + i * 16, sl + i * 8);
            }
            cp_commit_wait();
            __syncthreads();
        }
        mma_chunk(sbase + A2H_OFF + kc * 128, sbase + A2L_OFF + kc * 128, SA2,
                  sbase + BH_OFF, sbase + BL_OFF, C, r0, c0w, lane);
        __syncthreads();
    }

    // ================= Epilogue: bias + scatter-add =================
#pragma unroll
    for (int i = 0; i < 2; i++) {
        int row = r0 + i * 16 + (lane >> 2);
        int d0 = g_dst[e0 + row];
        int d1 = g_dst[e0 + row + 8];
#pragma unroll
        for (int j = 0; j < 8; j++) {
            int col = c0w + j * 8 + (lane & 3) * 2;
            float bb0 = b2[col], bb1 = b2[col + 1];
            red_add_v2(&g_agg[(size_t)d0 * H + col], C[i][j][0] + bb0, C[i][j][1] + bb1);
            red_add_v2(&g_agg[(size_t)d1 * H + col], C[i][j][2] + bb0, C[i][j][3] + bb1);
        }
    }
}

// ---------------------------------------------------------------------------
// Node kernel (tensor-core mma.sync): 128 nodes/block; h += MLP([h,agg]);
// zeroes agg in place; writes fp32 h + bf16 hi/lo split for next layer.
// ---------------------------------------------------------------------------
__global__ __launch_bounds__(256, 2)
void node_kernel_mma(const float* __restrict__ b1,
                     const float* __restrict__ b2, int layer) {
    extern __shared__ char smem[];
    const uint32_t sbase = smem_u32(smem);
    const int tid = threadIdx.x;
    const int lane = tid & 31;
    const int wid = tid >> 5;
    const int n0 = blockIdx.x * ET;

    const int srow = tid >> 1;
    const int shalf = tid & 1;
    const int snode = n0 + srow;
    const int scn = snode < N_NODES ? snode : (N_NODES - 1);

    const int r0 = (wid >> 1) * 32;
    const int c0w = (wid & 1) * 64;

    const uint32_t a1h = sbase + A1H_OFF + srow * (SA1 * 2) + shalf * 64;
    const uint32_t a1l = sbase + A1L_OFF + srow * (SA1 * 2) + shalf * 64;
    const uint32_t bsh = sbase + BH_OFF + srow * (SB * 2) + shalf * 64;
    const uint32_t bsl = sbase + BL_OFF + srow * (SB * 2) + shalf * 64;

    float C[2][8][4];
#pragma unroll
    for (int i = 0; i < 2; i++)
#pragma unroll
        for (int j = 0; j < 8; j++)
#pragma unroll
            for (int q = 0; q < 4; q++) C[i][j][q] = 0.0f;

    // ================= GEMM1: K=256 ([h | agg]) in 4 chunks =================
    for (int kc = 0; kc < 4; kc++) {
        if (kc < 2) {
            size_t goff = (size_t)scn * H + kc * 64 + shalf * 32;
            const __nv_bfloat16* sh = &g_hhi[goff];
            const __nv_bfloat16* sl = &g_hlo[goff];
#pragma unroll
            for (int i = 0; i < 4; i++) {
                cp16(a1h + i * 16, sh + i * 8);
                cp16(a1l + i * 16, sl + i * 8);
            }
        } else {
            // agg chunks: split on the fly + zero in place
            float4* hp = (float4*)&g_agg[(size_t)scn * H + (kc & 1) * 64 + shalf * 32];
            uint32_t ph[16], pl[16];
#pragma unroll
            for (int i = 0; i < 8; i++) {
                float4 v = hp[i];
                split2(v.x, v.y, ph[2 * i],     pl[2 * i]);
                split2(v.z, v.w, ph[2 * i + 1], pl[2 * i + 1]);
            }
            if (snode < N_NODES) {
                float4 z = make_float4(0.f, 0.f, 0.f, 0.f);
#pragma unroll
                for (int i = 0; i < 8; i++) hp[i] = z;
            }
            uint4* dh = (uint4*)(smem + A1H_OFF + srow * (SA1 * 2) + shalf * 64);
            uint4* dl = (uint4*)(smem + A1L_OFF + srow * (SA1 * 2) + shalf * 64);
#pragma unroll
            for (int i = 0; i < 4; i++) {
                dh[i] = make_uint4(ph[4 * i], ph[4 * i + 1], ph[4 * i + 2], ph[4 * i + 3]);
                dl[i] = make_uint4(pl[4 * i], pl[4 * i + 1], pl[4 * i + 2], pl[4 * i + 3]);
            }
        }
        {
            const __nv_bfloat16* sh = &g_nw1t[layer][0][srow][kc * 64 + shalf * 32];
            const __nv_bfloat16* sl = &g_nw1t[layer][1][srow][kc * 64 + shalf * 32];
#pragma unroll
            for (int i = 0; i < 4; i++) {
                cp16(bsh + i * 16, sh + i * 8);
                cp16(bsl + i * 16, sl + i * 8);
            }
        }
        cp_commit_wait();
        __syncthreads();
        mma_chunk(sbase + A1H_OFF, sbase + A1L_OFF, SA1,
                  sbase + BH_OFF, sbase + BL_OFF, C, r0, c0w, lane);
        __syncthreads();
    }

    // ===== Epilogue1 + stage GEMM2 B(kc=0) =====
    {
        const __nv_bfloat16* sh = &g_nw2t[layer][0][srow][shalf * 32];
        const __nv_bfloat16* sl = &g_nw2t[layer][1][srow][shalf * 32];
#pragma unroll
        for (int i = 0; i < 4; i++) {
            cp16(bsh + i * 16, sh + i * 8);
            cp16(bsl + i * 16, sl + i * 8);
        }
    }
#pragma unroll
    for (int i = 0; i < 2; i++)
#pragma unroll
        for (int j = 0; j < 8; j++) {
            int col = c0w + j * 8 + (lane & 3) * 2;
            int row = r0 + i * 16 + (lane >> 2);
            float bb0 = b1[col], bb1 = b1[col + 1];
            uint32_t hi, lo;
            split2(fmaxf(C[i][j][0] + bb0, 0.0f), fmaxf(C[i][j][1] + bb1, 0.0f), hi, lo);
            *(uint32_t*)(smem + A2H_OFF + row * (SA2 * 2) + col * 2) = hi;
            *(uint32_t*)(smem + A2L_OFF + row * (SA2 * 2) + col * 2) = lo;
            split2(fmaxf(C[i][j][2] + bb0, 0.0f), fmaxf(C[i][j][3] + bb1, 0.0f), hi, lo);
            *(uint32_t*)(smem + A2H_OFF + (row + 8) * (SA2 * 2) + col * 2) = hi;
            *(uint32_t*)(smem + A2L_OFF + (row + 8) * (SA2 * 2) + col * 2) = lo;
        }
    cp_commit_wait();
    __syncthreads();

    // ================= GEMM2: K=128 in 2 chunks =================
#pragma unroll
    for (int i = 0; i < 2; i++)
#pragma unroll
        for (int j = 0; j < 8; j++)
#pragma unroll
            for (int q = 0; q < 4; q++) C[i][j][q] = 0.0f;

    for (int kc = 0; kc < 2; kc++) {
        if (kc > 0) {
            const __nv_bfloat16* sh = &g_nw2t[layer][0][srow][kc * 64 + shalf * 32];
            const __nv_bfloat16* sl = &g_nw2t[layer][1][srow][kc * 64 + shalf * 32];
#pragma unroll
            for (int i = 0; i < 4; i++) {
                cp16(bsh + i * 16, sh + i * 8);
                cp16(bsl + i * 16, sl + i * 8);
            }
            cp_commit_wait();
            __syncthreads();
        }
        mma_chunk(sbase + A2H_OFF + kc * 128, sbase + A2L_OFF + kc * 128, SA2,
                  sbase + BH_OFF, sbase + BL_OFF, C, r0, c0w, lane);
        __syncthreads();
    }

    // ======== Epilogue2: residual h += C + b2; write fp32 + bf16 split ========
#pragma unroll
    for (int i = 0; i < 2; i++) {
        int row = r0 + i * 16 + (lane >> 2);
        int nd0 = n0 + row;
        int nd1 = n0 + row + 8;
#pragma unroll
        for (int j = 0; j < 8; j++) {
            int col = c0w + j * 8 + (lane & 3) * 2;
            float bb0 = b2[col], bb1 = b2[col + 1];
            if (nd0 < N_NODES) {
                size_t off = (size_t)nd0 * H + col;
                float2* p = (float2*)&g_h[off];
                float2 v = *p;
                v.x += C[i][j][0] + bb0;
                v.y += C[i][j][1] + bb1;
                *p = v;
                uint32_t hi, lo;
                split2(v.x, v.y, hi, lo);
                *(uint32_t*)&g_hhi[off] = hi;
                *(uint32_t*)&g_hlo[off] = lo;
            }
            if (nd1 < N_NODES) {
                size_t off = (size_t)nd1 * H + col;
                float2* p = (float2*)&g_h[off];
                float2 v = *p;
                v.x += C[i][j][2] + bb0;
                v.y += C[i][j][3] + bb1;
                *p = v;
                uint32_t hi, lo;
                split2(v.x, v.y, hi, lo);
                *(uint32_t*)&g_hhi[off] = hi;
                *(uint32_t*)&g_hlo[off] = lo;
            }
        }
    }
}

// ---------------------------------------------------------------------------
// Decoder
// ---------------------------------------------------------------------------
__global__ void dec_kernel(const float* __restrict__ w,
                           const float* __restrict__ b,
                           float* __restrict__ out) {
    int idx = blockIdx.x * blockDim.x + threadIdx.x;
    if (idx >= N_NODES * NODE_OUT) return;
    int node = idx / NODE_OUT;
    int j = idx - node * NODE_OUT;
    float acc = b[j];
    const float* hp = &g_h[(size_t)node * H];
#pragma unroll 8
    for (int k = 0; k < H; k++)
        acc = fmaf(hp[k], w[k * NODE_OUT + j], acc);
    out[idx] = acc;
}

// ---------------------------------------------------------------------------
extern "C" void kernel_launch(void* const* d_in, const int* in_sizes, int n_in,
                              void* d_out, int out_size) {
    const float* x      = (const float*)d_in[0];
    const void*  ei     = d_in[1];
    const float* enc_w  = (const float*)d_in[2];
    const float* enc_b  = (const float*)d_in[3];
    const float* dec_w  = (const float*)d_in[4];
    const float* dec_b  = (const float*)d_in[5];
    const float* e_w1   = (const float*)d_in[6];
    const float* e_b1   = (const float*)d_in[7];
    const float* e_w2   = (const float*)d_in[8];
    const float* e_b2   = (const float*)d_in[9];
    const float* n_w1   = (const float*)d_in[10];
    const float* n_b1   = (const float*)d_in[11];
    const float* n_w2   = (const float*)d_in[12];
    const float* n_b2   = (const float*)d_in[13];
    float*       out    = (float*)d_out;

    static int attr_set = 0;
    if (!attr_set) {
        cudaFuncSetAttribute(edge_kernel_mma, cudaFuncAttributeMaxDynamicSharedMemorySize,
                             EDGE_SMEM);
        cudaFuncSetAttribute(node_kernel_mma, cudaFuncAttributeMaxDynamicSharedMemorySize,
                             EDGE_SMEM);
        cudaFuncSetAttribute(prep_p_kernel, cudaFuncAttributeMaxDynamicSharedMemorySize,
                             PREP_SMEM);
        attr_set = 1;
    }

    detect_kernel<<<1, 32>>>(ei);
    convert_kernel<<<(2 * N_EDGES + 255) / 256, 256>>>(ei);
    prep_w_kernel<<<(2 * N_LAYERS * (2 * H * H + H * H) + 255) / 256, 256>>>(
        e_w1, e_w2, n_w1, n_w2);
    enc_kernel<<<(N_NODES * H + 255) / 256, 256>>>(x, enc_w, enc_b);

    const int node_blocks = (N_NODES + ET - 1) / ET;
    for (int l = 0; l < N_LAYERS; l++) {
        prep_p_kernel<<<node_blocks, 256, PREP_SMEM>>>(e_b1 + (size_t)l * H, l);
        edge_kernel_mma<<<N_EDGES / ET, 256, EDGE_SMEM>>>(
            e_b2 + (size_t)l * H, l);
        node_kernel_mma<<<node_blocks, 256, EDGE_SMEM>>>(
            n_b1 + (size_t)l * H, n_b2 + (size_t)l * H, l);
    }

    dec_kernel<<<(N_NODES * NODE_OUT + 255) / 256, 256>>>(dec_w, dec_b, out);
}